// round 3
// baseline (speedup 1.0000x reference)
#include <cuda_runtime.h>

// ---------------------------------------------------------------------------
// VisionSdpaAttention baseline (fp32 SIMT) + mask-dtype autodetect
//   L=1024, B=8, C=1024, H=16, D=64
// ---------------------------------------------------------------------------

// Scratch (static device globals; no runtime allocation)
__device__ float g_qkv[25165824];   // (L*B, 3C) = 8192 x 3072
__device__ float g_q[8388608];      // (B,H,L,D)
__device__ float g_k[8388608];
__device__ float g_v[8388608];
__device__ float g_attn[8388608];   // (L*B, C): row = l*B+b, col = h*64+d
__device__ unsigned char g_mask8[8388608];  // canonical mask (B,L,L), 1 = attend
__device__ int g_mask_mode;         // 0 = uint8, 1 = int32, 2 = float32

// ---------------------------------------------------------------------------
// Mask dtype detection: scan first 16KB of the raw buffer.
//  bool8   : bytes at offset%4==1 are ~50% nonzero
//  int32   : only offset%4==0 bytes can be 1; offsets 1..3 all zero
//  float32 : 1.0f = [00,00,80,3f]; offset3 bytes are 0x3f for True
// ---------------------------------------------------------------------------
__global__ void detect_mask_mode_kernel(const unsigned char* __restrict__ m)
{
    if (threadIdx.x != 0 || blockIdx.x != 0) return;
    bool off1_nonzero = false;
    bool off23_nonzero = false;
    for (int i = 0; i < 16384; i += 4) {
        if (m[i + 1] != 0) off1_nonzero = true;
        if (m[i + 2] != 0 || m[i + 3] != 0) off23_nonzero = true;
    }
    int mode;
    if (off1_nonzero)       mode = 0;  // uint8/bool
    else if (off23_nonzero) mode = 2;  // float32
    else                    mode = 1;  // int32
    g_mask_mode = mode;
}

__global__ __launch_bounds__(256) void convert_mask_kernel(const void* __restrict__ mp)
{
    const int i = blockIdx.x * 256 + threadIdx.x;
    const int mode = g_mask_mode;
    unsigned char v;
    if (mode == 0)      v = (((const unsigned char*)mp)[i] != 0);
    else if (mode == 1) v = (((const int*)mp)[i] != 0);
    else                v = (((const float*)mp)[i] != 0.0f);
    g_mask8[i] = v;
}

// ---------------------------------------------------------------------------
// SGEMM NT: C[m,n] = sum_k A[m,k] * B[n,k] + bias[n]
// BM=BN=128, BK=8, 256 threads, 8x8 per thread. M,N,K all divisible.
// ---------------------------------------------------------------------------
__global__ __launch_bounds__(256) void gemm_nt_bias(
    const float* __restrict__ A, const float* __restrict__ B,
    const float* __restrict__ bias, float* __restrict__ C,
    int M, int N, int K)
{
    __shared__ float As[8][128];
    __shared__ float Bs[8][128];
    const int bm = blockIdx.y * 128;
    const int bn = blockIdx.x * 128;
    const int tid = threadIdx.x;
    const int tx = tid & 15;
    const int ty = tid >> 4;
    const int lrow = tid >> 1;         // 0..127
    const int lcol = (tid & 1) * 4;    // 0 or 4

    const float* Aptr = A + (size_t)(bm + lrow) * K + lcol;
    const float* Bptr = B + (size_t)(bn + lrow) * K + lcol;

    float acc[8][8];
#pragma unroll
    for (int i = 0; i < 8; i++)
#pragma unroll
        for (int j = 0; j < 8; j++) acc[i][j] = 0.f;

    for (int k0 = 0; k0 < K; k0 += 8) {
        float4 a4 = *(const float4*)(Aptr + k0);
        float4 b4 = *(const float4*)(Bptr + k0);
        As[lcol + 0][lrow] = a4.x;
        As[lcol + 1][lrow] = a4.y;
        As[lcol + 2][lrow] = a4.z;
        As[lcol + 3][lrow] = a4.w;
        Bs[lcol + 0][lrow] = b4.x;
        Bs[lcol + 1][lrow] = b4.y;
        Bs[lcol + 2][lrow] = b4.z;
        Bs[lcol + 3][lrow] = b4.w;
        __syncthreads();
#pragma unroll
        for (int k = 0; k < 8; k++) {
            float4 a0 = *(const float4*)&As[k][ty * 8];
            float4 a1 = *(const float4*)&As[k][ty * 8 + 4];
            float4 b0 = *(const float4*)&Bs[k][tx * 8];
            float4 b1 = *(const float4*)&Bs[k][tx * 8 + 4];
            float av[8] = {a0.x, a0.y, a0.z, a0.w, a1.x, a1.y, a1.z, a1.w};
            float bv[8] = {b0.x, b0.y, b0.z, b0.w, b1.x, b1.y, b1.z, b1.w};
#pragma unroll
            for (int i = 0; i < 8; i++)
#pragma unroll
                for (int j = 0; j < 8; j++)
                    acc[i][j] += av[i] * bv[j];
        }
        __syncthreads();
    }

#pragma unroll
    for (int i = 0; i < 8; i++) {
        int m = bm + ty * 8 + i;
#pragma unroll
        for (int j = 0; j < 8; j += 4) {
            int n = bn + tx * 8 + j;
            float4 o;
            o.x = acc[i][j + 0] + bias[n + 0];
            o.y = acc[i][j + 1] + bias[n + 1];
            o.z = acc[i][j + 2] + bias[n + 2];
            o.w = acc[i][j + 3] + bias[n + 3];
            *(float4*)(C + (size_t)m * N + n) = o;
        }
    }
}

// ---------------------------------------------------------------------------
// RoPE + transpose: g_qkv (l*B+b, r) -> g_q/g_k/g_v (B,H,L,D)
// r = which*1024 + h*64 + d ;  cos/sin index = d mod 32 ; interleaved rotate
// ---------------------------------------------------------------------------
__global__ __launch_bounds__(256) void rope_transpose_kernel(const float* __restrict__ rpe)
{
    __shared__ float cs[32], sn[32];
    const int m = blockIdx.x;   // l*8 + b
    const int l = m >> 3;
    const int b = m & 7;
    const int tid = threadIdx.x;
    if (tid < 32) {
        float a = rpe[l * 32 + tid];
        cs[tid] = cosf(a);
        sn[tid] = sinf(a);
    }
    __syncthreads();
    const float* src = g_qkv + (size_t)m * 3072;
    for (int r = tid; r < 3072; r += 256) {
        int which = r >> 10;
        int hh = (r >> 6) & 15;
        int d = r & 63;
        float x = src[r];
        float val;
        if (which < 2) {
            float xp = src[r ^ 1];   // pair partner (2i <-> 2i+1)
            float c = cs[d & 31];
            float s = sn[d & 31];
            // even d: x*c - x[d+1]*s ;  odd d: x*c + x[d-1]*s
            val = x * c + ((d & 1) ? xp : -xp) * s;
        } else {
            val = x;
        }
        float* dst = (which == 0) ? g_q : (which == 1) ? g_k : g_v;
        dst[(((size_t)(b * 16 + hh)) * 1024 + l) * 64 + d] = val;
    }
}

// ---------------------------------------------------------------------------
// Flash attention per head. grid (128 heads, 16 q-tiles), 256 threads.
// 64x64 tiles, online softmax, 4x4 register micro-tile per thread.
// ---------------------------------------------------------------------------
__global__ __launch_bounds__(256) void attn_kernel()
{
    extern __shared__ float sm[];
    float* Qs = sm;
    float* Ks = sm + 64 * 65;
    float* Vs = sm + 2 * 64 * 65;
    float* Ps = sm + 3 * 64 * 65;

    const int bh = blockIdx.x;   // b*16 + h
    const int b = bh >> 4;
    const int h = bh & 15;
    const int qt = blockIdx.y;
    const int tid = threadIdx.x;
    const int tx = tid & 15;
    const int ty = tid >> 4;

    // Load Q tile (64 rows x 64 d)
    {
        const float* Qg = g_q + ((size_t)bh * 1024 + qt * 64) * 64;
        for (int v = tid; v < 64 * 16; v += 256) {
            int r = v >> 4;
            int dg = (v & 15) * 4;
            float4 t4 = *(const float4*)(Qg + r * 64 + dg);
            float* p = Qs + r * 65 + dg;
            p[0] = t4.x; p[1] = t4.y; p[2] = t4.z; p[3] = t4.w;
        }
    }

    float o[4][4];
    float mrow[4], lrow[4];
#pragma unroll
    for (int i = 0; i < 4; i++) {
        mrow[i] = -1e30f;
        lrow[i] = 0.f;
#pragma unroll
        for (int j = 0; j < 4; j++) o[i][j] = 0.f;
    }

    for (int kt = 0; kt < 16; kt++) {
        __syncthreads();   // protect Ks/Vs/Ps from previous iteration readers
        {
            const float* Kg = g_k + ((size_t)bh * 1024 + kt * 64) * 64;
            const float* Vg = g_v + ((size_t)bh * 1024 + kt * 64) * 64;
            for (int v = tid; v < 64 * 16; v += 256) {
                int r = v >> 4;
                int dg = (v & 15) * 4;
                float4 t4 = *(const float4*)(Kg + r * 64 + dg);
                float* p = Ks + r * 65 + dg;
                p[0] = t4.x; p[1] = t4.y; p[2] = t4.z; p[3] = t4.w;
                float4 u4 = *(const float4*)(Vg + r * 64 + dg);
                float* pv = Vs + r * 65 + dg;
                pv[0] = u4.x; pv[1] = u4.y; pv[2] = u4.z; pv[3] = u4.w;
            }
        }
        __syncthreads();

        // S = Q K^T (register 4x4 outer product over d)
        float s[4][4];
#pragma unroll
        for (int i = 0; i < 4; i++)
#pragma unroll
            for (int j = 0; j < 4; j++) s[i][j] = 0.f;

#pragma unroll 4
        for (int d = 0; d < 64; d++) {
            float qa[4], kb[4];
#pragma unroll
            for (int i = 0; i < 4; i++) qa[i] = Qs[(ty * 4 + i) * 65 + d];
#pragma unroll
            for (int j = 0; j < 4; j++) kb[j] = Ks[(tx + 16 * j) * 65 + d];
#pragma unroll
            for (int i = 0; i < 4; i++)
#pragma unroll
                for (int j = 0; j < 4; j++)
                    s[i][j] += qa[i] * kb[j];
        }

        // mask + scale (canonical uint8 mask: 1 = attend)
        const size_t mbase = ((size_t)b * 1024 + qt * 64) * 1024 + kt * 64;
#pragma unroll
        for (int i = 0; i < 4; i++) {
#pragma unroll
            for (int j = 0; j < 4; j++) {
                int r = ty * 4 + i;
                int c = tx + 16 * j;
                unsigned char mk = g_mask8[mbase + (size_t)r * 1024 + c];
                s[i][j] = mk ? s[i][j] * 0.125f : -1e30f;
            }
        }

        // online softmax per row (16 lanes of same ty share a row)
#pragma unroll
        for (int i = 0; i < 4; i++) {
            float tm = fmaxf(fmaxf(s[i][0], s[i][1]), fmaxf(s[i][2], s[i][3]));
            tm = fmaxf(tm, __shfl_xor_sync(0xffffffffu, tm, 8));
            tm = fmaxf(tm, __shfl_xor_sync(0xffffffffu, tm, 4));
            tm = fmaxf(tm, __shfl_xor_sync(0xffffffffu, tm, 2));
            tm = fmaxf(tm, __shfl_xor_sync(0xffffffffu, tm, 1));
            float mnew = fmaxf(mrow[i], tm);
            float alpha = __expf(mrow[i] - mnew);
            float rs = 0.f;
#pragma unroll
            for (int j = 0; j < 4; j++) {
                float p = __expf(s[i][j] - mnew);
                s[i][j] = p;
                rs += p;
            }
            rs += __shfl_xor_sync(0xffffffffu, rs, 8);
            rs += __shfl_xor_sync(0xffffffffu, rs, 4);
            rs += __shfl_xor_sync(0xffffffffu, rs, 2);
            rs += __shfl_xor_sync(0xffffffffu, rs, 1);
            lrow[i] = lrow[i] * alpha + rs;
            mrow[i] = mnew;
#pragma unroll
            for (int j = 0; j < 4; j++) o[i][j] *= alpha;
        }

        // share P
#pragma unroll
        for (int i = 0; i < 4; i++)
#pragma unroll
            for (int j = 0; j < 4; j++)
                Ps[(ty * 4 + i) * 65 + tx + 16 * j] = s[i][j];
        __syncthreads();

        // O += P V  (register 4x4 outer product over c)
#pragma unroll 4
        for (int c = 0; c < 64; c++) {
            float pa[4], vb[4];
#pragma unroll
            for (int i = 0; i < 4; i++) pa[i] = Ps[(ty * 4 + i) * 65 + c];
#pragma unroll
            for (int j = 0; j < 4; j++) vb[j] = Vs[c * 65 + tx + 16 * j];
#pragma unroll
            for (int i = 0; i < 4; i++)
#pragma unroll
                for (int j = 0; j < 4; j++)
                    o[i][j] += pa[i] * vb[j];
        }
    }

    // normalize + write to (L*B, C) layout: row = lq*8+b, col = h*64+dd
#pragma unroll
    for (int i = 0; i < 4; i++) {
        int lq = qt * 64 + ty * 4 + i;
        float inv = 1.f / lrow[i];
#pragma unroll
        for (int j = 0; j < 4; j++) {
            int dd = tx + 16 * j;
            g_attn[((size_t)lq * 8 + b) * 1024 + h * 64 + dd] = o[i][j] * inv;
        }
    }
}

// ---------------------------------------------------------------------------
// Launch
// ---------------------------------------------------------------------------
extern "C" void kernel_launch(void* const* d_in, const int* in_sizes, int n_in,
                              void* d_out, int out_size)
{
    const float* hs            = (const float*)d_in[0];  // (L,B,C)
    const float* rpe           = (const float*)d_in[1];  // (L, 32)
    const void* maskp          = d_in[2];                // (B,L,L) bool (dtype autodetected)
    const float* Wqkv          = (const float*)d_in[3];  // (3C, C)
    const float* bqkv          = (const float*)d_in[4];  // (3C)
    const float* Wo            = (const float*)d_in[5];  // (C, C)
    const float* bo            = (const float*)d_in[6];  // (C)
    float* out                 = (float*)d_out;          // (L,B,C)

    float *qkv_p, *attn_p;
    cudaGetSymbolAddress((void**)&qkv_p, g_qkv);
    cudaGetSymbolAddress((void**)&attn_p, g_attn);

    // Stage 0: mask canonicalization
    detect_mask_mode_kernel<<<1, 32>>>((const unsigned char*)maskp);
    convert_mask_kernel<<<8388608 / 256, 256>>>(maskp);

    // Stage 1: QKV projection  (M=8192, N=3072, K=1024)
    {
        dim3 grid(3072 / 128, 8192 / 128);
        gemm_nt_bias<<<grid, 256>>>(hs, Wqkv, bqkv, qkv_p, 8192, 3072, 1024);
    }

    // Stage 2: RoPE + transpose
    rope_transpose_kernel<<<8192, 256>>>(rpe);

    // Stage 3: attention
    {
        const int smem = 4 * 64 * 65 * sizeof(float);  // 66560 B
        cudaFuncSetAttribute(attn_kernel,
                             cudaFuncAttributeMaxDynamicSharedMemorySize, smem);
        dim3 grid(128, 16);
        attn_kernel<<<grid, 256, smem>>>();
    }

    // Stage 4: output projection  (M=8192, N=1024, K=1024)
    {
        dim3 grid(1024 / 128, 8192 / 128);
        gemm_nt_bias<<<grid, 256>>>(attn_p, Wo, bo, out, 8192, 1024, 1024);
    }
}

// round 4
// speedup vs baseline: 1.3842x; 1.3842x over previous
#include <cuda_runtime.h>
#include <mma.h>

using namespace nvcuda;

// ---------------------------------------------------------------------------
// VisionSdpaAttention — TF32 tensor-core version
//   L=1024, B=8, C=1024, H=16, D=64
//   Stage 1: qkv = hs @ Wqkv^T + bqkv   (wmma tf32, 8192 x 3072, K=1024)
//   Stage 2: RoPE + transpose -> (B,H,L,D)
//   Stage 3: flash attention (wmma tf32 for QK^T and PV)
//   Stage 4: out = attn @ Wo^T + bo     (wmma tf32, 8192 x 1024, K=1024)
// ---------------------------------------------------------------------------

__device__ float g_qkv[25165824];   // (L*B, 3C)
__device__ float g_q[8388608];      // (B,H,L,D)
__device__ float g_k[8388608];
__device__ float g_v[8388608];
__device__ float g_attn[8388608];   // (L*B, C)
__device__ unsigned char g_mask8[8388608];
__device__ int g_mask_mode;

__device__ __forceinline__ float to_tf32(float x) {
    unsigned int u;
    asm("cvt.rna.tf32.f32 %0, %1;" : "=r"(u) : "f"(x));
    return __uint_as_float(u);
}

// ---------------------------------------------------------------------------
// Mask dtype detection + canonicalization (unchanged from R2)
// ---------------------------------------------------------------------------
__global__ void detect_mask_mode_kernel(const unsigned char* __restrict__ m)
{
    if (threadIdx.x != 0 || blockIdx.x != 0) return;
    bool off1_nonzero = false, off23_nonzero = false;
    for (int i = 0; i < 16384; i += 4) {
        if (m[i + 1] != 0) off1_nonzero = true;
        if (m[i + 2] != 0 || m[i + 3] != 0) off23_nonzero = true;
    }
    g_mask_mode = off1_nonzero ? 0 : (off23_nonzero ? 2 : 1);
}

__global__ __launch_bounds__(256) void convert_mask_kernel(const void* __restrict__ mp)
{
    const int i = blockIdx.x * 256 + threadIdx.x;
    const int mode = g_mask_mode;
    unsigned char v;
    if (mode == 0)      v = (((const unsigned char*)mp)[i] != 0);
    else if (mode == 1) v = (((const int*)mp)[i] != 0);
    else                v = (((const float*)mp)[i] != 0.0f);
    g_mask8[i] = v;
}

// ---------------------------------------------------------------------------
// TF32 WMMA GEMM NT: C[m,n] = sum_k A[m,k]*B[n,k] + bias[n]
// BM=BN=128, BK=32, 256 threads (8 warps: 4 along M x 2 along N).
// Warp tile 32x64 = 2x4 fragments of m16n16k8.
// Dynamic smem: As[128][36] + Bs[128][36] (main) aliased with Cs[128][132].
// ---------------------------------------------------------------------------
#define GLDA 36
#define GLDC 132

__global__ __launch_bounds__(256) void gemm_nt_bias_tf32(
    const float* __restrict__ A, const float* __restrict__ B,
    const float* __restrict__ bias, float* __restrict__ C,
    int M, int N, int K)
{
    extern __shared__ float sg[];
    float* As = sg;                 // [128][36]
    float* Bs = sg + 128 * GLDA;    // [128][36]
    float* Cs = sg;                 // [128][132] (aliases As/Bs after k-loop)

    const int bm = blockIdx.y * 128;
    const int bn = blockIdx.x * 128;
    const int tid = threadIdx.x;
    const int wid = tid >> 5;
    const int warpM = wid & 3;       // 0..3
    const int warpN = wid >> 2;      // 0..1

    wmma::fragment<wmma::accumulator, 16, 16, 8, float> acc[2][4];
#pragma unroll
    for (int i = 0; i < 2; i++)
#pragma unroll
        for (int j = 0; j < 4; j++) wmma::fill_fragment(acc[i][j], 0.0f);

    for (int k0 = 0; k0 < K; k0 += 32) {
        // load 128x32 tiles of A and B (float4, tf32-rounded into smem)
#pragma unroll
        for (int i = 0; i < 4; i++) {
            int s = tid + i * 256;          // 0..1023
            int row = s >> 3;
            int col = (s & 7) * 4;
            float4 a4 = *(const float4*)(A + (size_t)(bm + row) * K + k0 + col);
            float4 b4 = *(const float4*)(B + (size_t)(bn + row) * K + k0 + col);
            float* pa = As + row * GLDA + col;
            pa[0] = to_tf32(a4.x); pa[1] = to_tf32(a4.y);
            pa[2] = to_tf32(a4.z); pa[3] = to_tf32(a4.w);
            float* pb = Bs + row * GLDA + col;
            pb[0] = to_tf32(b4.x); pb[1] = to_tf32(b4.y);
            pb[2] = to_tf32(b4.z); pb[3] = to_tf32(b4.w);
        }
        __syncthreads();

#pragma unroll
        for (int ks = 0; ks < 4; ks++) {
            wmma::fragment<wmma::matrix_a, 16, 16, 8, wmma::precision::tf32, wmma::row_major> af[2];
            wmma::fragment<wmma::matrix_b, 16, 16, 8, wmma::precision::tf32, wmma::col_major> bf[4];
#pragma unroll
            for (int i = 0; i < 2; i++)
                wmma::load_matrix_sync(af[i], As + (warpM * 32 + i * 16) * GLDA + ks * 8, GLDA);
#pragma unroll
            for (int j = 0; j < 4; j++)
                wmma::load_matrix_sync(bf[j], Bs + (warpN * 64 + j * 16) * GLDA + ks * 8, GLDA);
#pragma unroll
            for (int i = 0; i < 2; i++)
#pragma unroll
                for (int j = 0; j < 4; j++)
                    wmma::mma_sync(acc[i][j], af[i], bf[j], acc[i][j]);
        }
        __syncthreads();
    }

    // epilogue via smem staging (Cs aliases As/Bs)
#pragma unroll
    for (int i = 0; i < 2; i++)
#pragma unroll
        for (int j = 0; j < 4; j++)
            wmma::store_matrix_sync(Cs + (warpM * 32 + i * 16) * GLDC + warpN * 64 + j * 16,
                                    acc[i][j], GLDC, wmma::mem_row_major);
    __syncthreads();

#pragma unroll
    for (int i = 0; i < 16; i++) {
        int s = tid + i * 256;          // 0..4095 float4 slots
        int row = s >> 5;
        int col = (s & 31) * 4;
        int n = bn + col;
        float* pc = Cs + row * GLDC + col;
        float4 o;
        o.x = pc[0] + bias[n + 0];
        o.y = pc[1] + bias[n + 1];
        o.z = pc[2] + bias[n + 2];
        o.w = pc[3] + bias[n + 3];
        *(float4*)(C + (size_t)(bm + row) * N + n) = o;
    }
}

// ---------------------------------------------------------------------------
// RoPE + transpose (unchanged)
// ---------------------------------------------------------------------------
__global__ __launch_bounds__(256) void rope_transpose_kernel(const float* __restrict__ rpe)
{
    __shared__ float cs[32], sn[32];
    const int m = blockIdx.x;   // l*8 + b
    const int l = m >> 3;
    const int b = m & 7;
    const int tid = threadIdx.x;
    if (tid < 32) {
        float a = rpe[l * 32 + tid];
        cs[tid] = cosf(a);
        sn[tid] = sinf(a);
    }
    __syncthreads();
    const float* src = g_qkv + (size_t)m * 3072;
    for (int r = tid; r < 3072; r += 256) {
        int which = r >> 10;
        int hh = (r >> 6) & 15;
        int d = r & 63;
        float x = src[r];
        float val;
        if (which < 2) {
            float xp = src[r ^ 1];
            float c = cs[d & 31];
            float s = sn[d & 31];
            val = x * c + ((d & 1) ? xp : -xp) * s;
        } else {
            val = x;
        }
        float* dst = (which == 0) ? g_q : (which == 1) ? g_k : g_v;
        dst[(((size_t)(b * 16 + hh)) * 1024 + l) * 64 + d] = val;
    }
}

// ---------------------------------------------------------------------------
// Flash attention with TF32 wmma for S=QK^T and O+=PV.
// grid (128 heads, 16 q-tiles), 256 threads (8 warps).
// Tiles 64x64, ld=68. S frag grid 4x4; warp w owns frow=w&3, fcols {(w>>2)*2, +1}.
// Softmax: thread t owns row=t>>2, cols (t&3)*16..+15 (quad shfl reduce).
// smem: Qs,Ks,Vs,Ss,Os [64][68] + sM,sL,sAlpha[64]  = 87808 B
// ---------------------------------------------------------------------------
#define ALD 68

__global__ __launch_bounds__(256) void attn_kernel_tf32()
{
    extern __shared__ float sm[];
    float* Qs = sm;
    float* Ks = sm + 64 * ALD;
    float* Vs = sm + 2 * 64 * ALD;
    float* Ss = sm + 3 * 64 * ALD;
    float* Os = sm + 4 * 64 * ALD;
    float* sM = sm + 5 * 64 * ALD;
    float* sL = sM + 64;
    float* sAl = sL + 64;

    const int bh = blockIdx.x;   // b*16 + h
    const int b = bh >> 4;
    const int h = bh & 15;
    const int qt = blockIdx.y;
    const int tid = threadIdx.x;
    const int wid = tid >> 5;
    const int frow = wid & 3;
    const int fcol2 = (wid >> 2) * 2;
    const int srow = tid >> 2;        // softmax row 0..63
    const int squad = tid & 3;        // quarter 0..3

    // init: load Q (tf32), zero O, init stats
    {
        const float* Qg = g_q + ((size_t)bh * 1024 + qt * 64) * 64;
#pragma unroll
        for (int i = 0; i < 4; i++) {
            int s = tid + i * 256;       // 0..1023 float4 slots
            int r = s >> 4;
            int c = (s & 15) * 4;
            float4 t4 = *(const float4*)(Qg + r * 64 + c);
            float* p = Qs + r * ALD + c;
            p[0] = to_tf32(t4.x); p[1] = to_tf32(t4.y);
            p[2] = to_tf32(t4.z); p[3] = to_tf32(t4.w);
            float* po = Os + r * ALD + c;
            po[0] = 0.f; po[1] = 0.f; po[2] = 0.f; po[3] = 0.f;
        }
        if (tid < 64) { sM[tid] = -1e30f; sL[tid] = 0.f; }
    }

    for (int kt = 0; kt < 16; kt++) {
        __syncthreads();
        // load K, V tiles (tf32)
        {
            const float* Kg = g_k + ((size_t)bh * 1024 + kt * 64) * 64;
            const float* Vg = g_v + ((size_t)bh * 1024 + kt * 64) * 64;
#pragma unroll
            for (int i = 0; i < 4; i++) {
                int s = tid + i * 256;
                int r = s >> 4;
                int c = (s & 15) * 4;
                float4 t4 = *(const float4*)(Kg + r * 64 + c);
                float* p = Ks + r * ALD + c;
                p[0] = to_tf32(t4.x); p[1] = to_tf32(t4.y);
                p[2] = to_tf32(t4.z); p[3] = to_tf32(t4.w);
                float4 u4 = *(const float4*)(Vg + r * 64 + c);
                float* pv = Vs + r * ALD + c;
                pv[0] = to_tf32(u4.x); pv[1] = to_tf32(u4.y);
                pv[2] = to_tf32(u4.z); pv[3] = to_tf32(u4.w);
            }
        }
        __syncthreads();

        // S = Q K^T  (each warp: 2 frags of 16x16, k=64 in 8 steps)
        {
            wmma::fragment<wmma::accumulator, 16, 16, 8, float> sacc[2];
            wmma::fill_fragment(sacc[0], 0.0f);
            wmma::fill_fragment(sacc[1], 0.0f);
#pragma unroll
            for (int ks = 0; ks < 8; ks++) {
                wmma::fragment<wmma::matrix_a, 16, 16, 8, wmma::precision::tf32, wmma::row_major> qf;
                wmma::load_matrix_sync(qf, Qs + (frow * 16) * ALD + ks * 8, ALD);
#pragma unroll
                for (int j = 0; j < 2; j++) {
                    wmma::fragment<wmma::matrix_b, 16, 16, 8, wmma::precision::tf32, wmma::col_major> kf;
                    wmma::load_matrix_sync(kf, Ks + ((fcol2 + j) * 16) * ALD + ks * 8, ALD);
                    wmma::mma_sync(sacc[j], qf, kf, sacc[j]);
                }
            }
#pragma unroll
            for (int j = 0; j < 2; j++)
                wmma::store_matrix_sync(Ss + (frow * 16) * ALD + (fcol2 + j) * 16,
                                        sacc[j], ALD, wmma::mem_row_major);
        }
        __syncthreads();

        // softmax: mask + scale + online update; P written back to Ss (tf32)
        {
            const int cbase = squad * 16;
            const unsigned char* mrow_p =
                g_mask8 + ((size_t)b * 1024 + qt * 64 + srow) * 1024 + kt * 64 + cbase;
            uint4 mk4 = *(const uint4*)mrow_p;
            unsigned char mk[16];
            *(uint4*)mk = mk4;

            float* srow_p = Ss + srow * ALD + cbase;
            float vals[16];
#pragma unroll
            for (int i = 0; i < 16; i++)
                vals[i] = mk[i] ? srow_p[i] * 0.125f : -1e30f;

            float tmax = vals[0];
#pragma unroll
            for (int i = 1; i < 16; i++) tmax = fmaxf(tmax, vals[i]);
            tmax = fmaxf(tmax, __shfl_xor_sync(0xffffffffu, tmax, 1));
            tmax = fmaxf(tmax, __shfl_xor_sync(0xffffffffu, tmax, 2));

            float mold = sM[srow];
            float mnew = fmaxf(mold, tmax);
            float alpha = __expf(mold - mnew);
            float rs = 0.f;
#pragma unroll
            for (int i = 0; i < 16; i++) {
                float p = __expf(vals[i] - mnew);
                srow_p[i] = to_tf32(p);
                rs += p;
            }
            rs += __shfl_xor_sync(0xffffffffu, rs, 1);
            rs += __shfl_xor_sync(0xffffffffu, rs, 2);
            if (squad == 0) {
                sM[srow] = mnew;
                sL[srow] = sL[srow] * alpha + rs;
                sAl[srow] = alpha;
            }
        }
        __syncthreads();

        // scale O by alpha (per row)
        {
            float a = sAl[srow];
            float* orow = Os + srow * ALD + squad * 16;
#pragma unroll
            for (int i = 0; i < 16; i++) orow[i] *= a;
        }
        __syncthreads();

        // O += P V  (accumulator loaded from / stored to Os)
        {
#pragma unroll
            for (int j = 0; j < 2; j++) {
                wmma::fragment<wmma::accumulator, 16, 16, 8, float> oacc;
                wmma::load_matrix_sync(oacc, Os + (frow * 16) * ALD + (fcol2 + j) * 16,
                                       ALD, wmma::mem_row_major);
#pragma unroll
                for (int ks = 0; ks < 8; ks++) {
                    wmma::fragment<wmma::matrix_a, 16, 16, 8, wmma::precision::tf32, wmma::row_major> pf;
                    wmma::fragment<wmma::matrix_b, 16, 16, 8, wmma::precision::tf32, wmma::row_major> vf;
                    wmma::load_matrix_sync(pf, Ss + (frow * 16) * ALD + ks * 8, ALD);
                    wmma::load_matrix_sync(vf, Vs + (ks * 8) * ALD + (fcol2 + j) * 16, ALD);
                    wmma::mma_sync(oacc, pf, vf, oacc);
                }
                wmma::store_matrix_sync(Os + (frow * 16) * ALD + (fcol2 + j) * 16,
                                        oacc, ALD, wmma::mem_row_major);
            }
        }
    }
    __syncthreads();

    // normalize + write out: row = (qt*64+srow)*8 + b, col = h*64 + c
    {
        float inv = 1.f / sL[srow];
        int lq = qt * 64 + srow;
        float* orow = Os + srow * ALD + squad * 16;
        float* dst = g_attn + ((size_t)lq * 8 + b) * 1024 + h * 64 + squad * 16;
#pragma unroll
        for (int i = 0; i < 16; i += 4) {
            float4 o;
            o.x = orow[i + 0] * inv;
            o.y = orow[i + 1] * inv;
            o.z = orow[i + 2] * inv;
            o.w = orow[i + 3] * inv;
            *(float4*)(dst + i) = o;
        }
    }
}

// ---------------------------------------------------------------------------
// Launch
// ---------------------------------------------------------------------------
extern "C" void kernel_launch(void* const* d_in, const int* in_sizes, int n_in,
                              void* d_out, int out_size)
{
    const float* hs   = (const float*)d_in[0];
    const float* rpe  = (const float*)d_in[1];
    const void* maskp = d_in[2];
    const float* Wqkv = (const float*)d_in[3];
    const float* bqkv = (const float*)d_in[4];
    const float* Wo   = (const float*)d_in[5];
    const float* bo   = (const float*)d_in[6];
    float* out        = (float*)d_out;

    float *qkv_p, *attn_p;
    cudaGetSymbolAddress((void**)&qkv_p, g_qkv);
    cudaGetSymbolAddress((void**)&attn_p, g_attn);

    // Stage 0: mask canonicalization
    detect_mask_mode_kernel<<<1, 32>>>((const unsigned char*)maskp);
    convert_mask_kernel<<<8388608 / 256, 256>>>(maskp);

    const int gemm_smem = 128 * GLDC * sizeof(float);  // 67584 (>= As+Bs)
    cudaFuncSetAttribute(gemm_nt_bias_tf32,
                         cudaFuncAttributeMaxDynamicSharedMemorySize, gemm_smem);

    // Stage 1: QKV projection
    {
        dim3 grid(3072 / 128, 8192 / 128);
        gemm_nt_bias_tf32<<<grid, 256, gemm_smem>>>(hs, Wqkv, bqkv, qkv_p, 8192, 3072, 1024);
    }

    // Stage 2: RoPE + transpose
    rope_transpose_kernel<<<8192, 256>>>(rpe);

    // Stage 3: attention
    {
        const int smem = (5 * 64 * ALD + 3 * 64) * sizeof(float);  // 87808
        cudaFuncSetAttribute(attn_kernel_tf32,
                             cudaFuncAttributeMaxDynamicSharedMemorySize, smem);
        dim3 grid(128, 16);
        attn_kernel_tf32<<<grid, 256, smem>>>();
    }

    // Stage 4: output projection
    {
        dim3 grid(1024 / 128, 8192 / 128);
        gemm_nt_bias_tf32<<<grid, 256, gemm_smem>>>(attn_p, Wo, bo, out, 8192, 1024, 1024);
    }
}

// round 5
// speedup vs baseline: 1.7556x; 1.2683x over previous
#include <cuda_runtime.h>
#include <mma.h>

using namespace nvcuda;

// ---------------------------------------------------------------------------
// VisionSdpaAttention — TF32 tensor-core v2
//   L=1024, B=8, C=1024, H=16, D=64
//   gemm1 (cp.async double-buffered, no bias) -> rope(+bqkv) ->
//   attention (mma.sync m16n8k8 tf32, register-resident FA2) ->
//   gemm2 -> bias_add(bo)
// ---------------------------------------------------------------------------

__device__ float g_qkv[25165824];             // (L*B, 3C)
__device__ float g_q[8388608];                // (B,H,L,D)
__device__ float g_k[8388608];
__device__ float g_v[8388608];
__device__ float g_attn[8388608];             // (L*B, C)
__device__ unsigned long long g_maskbits[131072];  // [B][L][16 chunks of 64 cols]
__device__ int g_mask_mode;

__device__ __forceinline__ float to_tf32(float x) {
    unsigned int u;
    asm("cvt.rna.tf32.f32 %0, %1;" : "=r"(u) : "f"(x));
    return __uint_as_float(u);
}

__device__ __forceinline__ void cp_async16(void* sptr, const void* gptr) {
    unsigned s = (unsigned)__cvta_generic_to_shared(sptr);
    asm volatile("cp.async.cg.shared.global [%0], [%1], 16;" :: "r"(s), "l"(gptr));
}
__device__ __forceinline__ void cp_commit() {
    asm volatile("cp.async.commit_group;");
}

// mma.sync m16n8k8 tf32: D = A(16x8) * B(8x8) + D
__device__ __forceinline__ void mma8(float* c, const unsigned* a, unsigned b0, unsigned b1) {
    asm volatile(
        "mma.sync.aligned.m16n8k8.row.col.f32.tf32.tf32.f32 "
        "{%0,%1,%2,%3},{%4,%5,%6,%7},{%8,%9},{%0,%1,%2,%3};"
        : "+f"(c[0]), "+f"(c[1]), "+f"(c[2]), "+f"(c[3])
        : "r"(a[0]), "r"(a[1]), "r"(a[2]), "r"(a[3]), "r"(b0), "r"(b1));
}

// ---------------------------------------------------------------------------
// Mask dtype detection + bitpack: bit j of chunk = mask[row, chunk*64 + j]
// ---------------------------------------------------------------------------
__global__ void detect_mask_mode_kernel(const unsigned char* __restrict__ m)
{
    if (threadIdx.x != 0 || blockIdx.x != 0) return;
    bool off1 = false, off23 = false;
    for (int i = 0; i < 16384; i += 4) {
        if (m[i + 1] != 0) off1 = true;
        if (m[i + 2] != 0 || m[i + 3] != 0) off23 = true;
    }
    g_mask_mode = off1 ? 0 : (off23 ? 2 : 1);
}

__global__ __launch_bounds__(256) void convert_mask_bits_kernel(const void* __restrict__ mp)
{
    const int idx = blockIdx.x * 256 + threadIdx.x;   // 0..131071
    const int mode = g_mask_mode;
    unsigned long long bits = 0ULL;
    const size_t base = (size_t)idx * 64;
    if (mode == 0) {
        const uint4* p = (const uint4*)((const unsigned char*)mp + base);
#pragma unroll
        for (int wrd = 0; wrd < 4; wrd++) {
            uint4 v = p[wrd];
            unsigned ws[4] = {v.x, v.y, v.z, v.w};
#pragma unroll
            for (int q = 0; q < 4; q++)
#pragma unroll
                for (int by = 0; by < 4; by++)
                    if ((ws[q] >> (by * 8)) & 0xffu)
                        bits |= 1ULL << (wrd * 16 + q * 4 + by);
        }
    } else if (mode == 1) {
        const int* p = (const int*)mp + base;
#pragma unroll 8
        for (int j = 0; j < 64; j++)
            if (p[j] != 0) bits |= 1ULL << j;
    } else {
        const float* p = (const float*)mp + base;
#pragma unroll 8
        for (int j = 0; j < 64; j++)
            if (p[j] != 0.0f) bits |= 1ULL << j;
    }
    g_maskbits[idx] = bits;
}

// ---------------------------------------------------------------------------
// TF32 WMMA GEMM NT (no bias): C[m,n] = sum_k A[m,k]*B[n,k]
// BM=BN=128, BK=32, 256 threads, cp.async double buffer, direct frag stores.
// ---------------------------------------------------------------------------
#define GLDA 36
#define GSTAGE (128 * GLDA)

__global__ __launch_bounds__(256) void gemm_nt_tf32(
    const float* __restrict__ A, const float* __restrict__ B,
    float* __restrict__ C, int M, int N, int K)
{
    extern __shared__ float sg[];
    float* Asb[2] = { sg,               sg + GSTAGE };
    float* Bsb[2] = { sg + 2 * GSTAGE,  sg + 3 * GSTAGE };

    const int bm = blockIdx.y * 128;
    const int bn = blockIdx.x * 128;
    const int tid = threadIdx.x;
    const int wid = tid >> 5;
    const int warpM = wid & 3;
    const int warpN = wid >> 2;

    wmma::fragment<wmma::accumulator, 16, 16, 8, float> acc[2][4];
#pragma unroll
    for (int i = 0; i < 2; i++)
#pragma unroll
        for (int j = 0; j < 4; j++) wmma::fill_fragment(acc[i][j], 0.0f);

    const int nk = K / 32;

    // prologue: stage 0
    {
#pragma unroll
        for (int i = 0; i < 4; i++) {
            int e = tid + i * 256;
            int r = e >> 3, c = (e & 7) * 4;
            cp_async16(Asb[0] + r * GLDA + c, A + (size_t)(bm + r) * K + c);
            cp_async16(Bsb[0] + r * GLDA + c, B + (size_t)(bn + r) * K + c);
        }
        cp_commit();
    }

    for (int it = 0; it < nk; it++) {
        if (it + 1 < nk) {
            const int k0n = (it + 1) * 32;
            float* An = Asb[(it + 1) & 1];
            float* Bn = Bsb[(it + 1) & 1];
#pragma unroll
            for (int i = 0; i < 4; i++) {
                int e = tid + i * 256;
                int r = e >> 3, c = (e & 7) * 4;
                cp_async16(An + r * GLDA + c, A + (size_t)(bm + r) * K + k0n + c);
                cp_async16(Bn + r * GLDA + c, B + (size_t)(bn + r) * K + k0n + c);
            }
            cp_commit();
            asm volatile("cp.async.wait_group 1;");
        } else {
            asm volatile("cp.async.wait_group 0;");
        }
        __syncthreads();

        const float* As = Asb[it & 1];
        const float* Bs = Bsb[it & 1];
#pragma unroll
        for (int ks = 0; ks < 4; ks++) {
            wmma::fragment<wmma::matrix_a, 16, 16, 8, wmma::precision::tf32, wmma::row_major> af[2];
            wmma::fragment<wmma::matrix_b, 16, 16, 8, wmma::precision::tf32, wmma::col_major> bf[4];
#pragma unroll
            for (int i = 0; i < 2; i++) {
                wmma::load_matrix_sync(af[i], As + (warpM * 32 + i * 16) * GLDA + ks * 8, GLDA);
#pragma unroll
                for (int e = 0; e < af[i].num_elements; e++) af[i].x[e] = to_tf32(af[i].x[e]);
            }
#pragma unroll
            for (int j = 0; j < 4; j++) {
                wmma::load_matrix_sync(bf[j], Bs + (warpN * 64 + j * 16) * GLDA + ks * 8, GLDA);
#pragma unroll
                for (int e = 0; e < bf[j].num_elements; e++) bf[j].x[e] = to_tf32(bf[j].x[e]);
            }
#pragma unroll
            for (int i = 0; i < 2; i++)
#pragma unroll
                for (int j = 0; j < 4; j++)
                    wmma::mma_sync(acc[i][j], af[i], bf[j], acc[i][j]);
        }
        __syncthreads();
    }

    // direct stores (bias deferred to consumers)
#pragma unroll
    for (int i = 0; i < 2; i++)
#pragma unroll
        for (int j = 0; j < 4; j++)
            wmma::store_matrix_sync(
                C + (size_t)(bm + warpM * 32 + i * 16) * N + bn + warpN * 64 + j * 16,
                acc[i][j], N, wmma::mem_row_major);
}

// ---------------------------------------------------------------------------
// RoPE + bias + transpose: g_qkv (l*B+b, r) + bqkv -> g_q/g_k/g_v (B,H,L,D)
// ---------------------------------------------------------------------------
__global__ __launch_bounds__(256) void rope_bias_transpose_kernel(
    const float* __restrict__ rpe, const float* __restrict__ bq)
{
    __shared__ float cs[32], sn[32];
    const int m = blockIdx.x;   // l*8 + b
    const int l = m >> 3;
    const int b = m & 7;
    const int tid = threadIdx.x;
    if (tid < 32) {
        float a = rpe[l * 32 + tid];
        cs[tid] = cosf(a);
        sn[tid] = sinf(a);
    }
    __syncthreads();
    const float* src = g_qkv + (size_t)m * 3072;
    for (int r = tid; r < 3072; r += 256) {
        int which = r >> 10;
        int hh = (r >> 6) & 15;
        int d = r & 63;
        float x = src[r] + bq[r];
        float val;
        if (which < 2) {
            float xp = src[r ^ 1] + bq[r ^ 1];
            float c = cs[d & 31];
            float s = sn[d & 31];
            val = x * c + ((d & 1) ? xp : -xp) * s;
        } else {
            val = x;
        }
        float* dst = (which == 0) ? g_q : (which == 1) ? g_k : g_v;
        dst[(((size_t)(b * 16 + hh)) * 1024 + l) * 64 + d] = val;
    }
}

// ---------------------------------------------------------------------------
// Flash attention, register-resident (FA2 style), mma.m16n8k8 tf32.
// grid (128 heads, 16 q-tiles), 128 threads (4 warps); warp w owns q rows
// [w*16, w*16+16). smem: Qs(=P) [64][68], Ks [64][68], Vs [64][72].
// Fragment index math (PTX m16n8k8 tf32): g=lane>>2, t=lane&3.
//   A: a0(g,t) a1(g+8,t) a2(g,t+4) a3(g+8,t+4)
//   B: b0(t,g) b1(t+4,g)   C: c0(g,2t) c1(g,2t+1) c2(g+8,2t) c3(g+8,2t+1)
// ---------------------------------------------------------------------------
#define AKL 68
#define AVL 72

__global__ __launch_bounds__(128) void attn_tf32_reg()
{
    extern __shared__ float sm[];
    float* Qs = sm;                    // 64*68 (doubles as P, per-warp strips)
    float* Ks = sm + 64 * AKL;         // 64*68
    float* Vs = sm + 2 * 64 * AKL;     // 64*72

    const int bh = blockIdx.x;   // b*16 + h
    const int b = bh >> 4;
    const int h = bh & 15;
    const int qt = blockIdx.y;
    const int tid = threadIdx.x;
    const int w = tid >> 5;
    const int lane = tid & 31;
    const int g = lane >> 2;
    const int t = lane & 3;

    // load Q tile -> smem (tf32)
    {
        const float* Qg = g_q + ((size_t)bh * 1024 + qt * 64) * 64;
#pragma unroll
        for (int i = 0; i < 8; i++) {
            int e = tid + i * 128;         // 0..1023 float4 slots
            int r = e >> 4, c = (e & 15) * 4;
            float4 v = *(const float4*)(Qg + r * 64 + c);
            float* p = Qs + r * AKL + c;
            p[0] = to_tf32(v.x); p[1] = to_tf32(v.y);
            p[2] = to_tf32(v.z); p[3] = to_tf32(v.w);
        }
    }
    __syncthreads();

    // Q A-fragments, register-resident for whole kernel
    unsigned qa[8][4];
    {
        const float* Qw = Qs + (w * 16) * AKL;
#pragma unroll
        for (int ks = 0; ks < 8; ks++) {
            qa[ks][0] = __float_as_uint(Qw[g * AKL + ks * 8 + t]);
            qa[ks][1] = __float_as_uint(Qw[(g + 8) * AKL + ks * 8 + t]);
            qa[ks][2] = __float_as_uint(Qw[g * AKL + ks * 8 + t + 4]);
            qa[ks][3] = __float_as_uint(Qw[(g + 8) * AKL + ks * 8 + t + 4]);
        }
    }
    __syncthreads();   // everyone done reading Qs before it becomes P

    float o[8][4];
#pragma unroll
    for (int j = 0; j < 8; j++) { o[j][0] = 0.f; o[j][1] = 0.f; o[j][2] = 0.f; o[j][3] = 0.f; }
    float mr0 = -1e30f, mr1 = -1e30f, l0 = 0.f, l1 = 0.f;

    const float* Kg = g_k + (size_t)bh * 1024 * 64;
    const float* Vg = g_v + (size_t)bh * 1024 * 64;
    const int row0 = qt * 64 + w * 16 + g;
    const size_t mb_base0 = ((size_t)b * 1024 + row0) * 16;
    const size_t mb_base1 = ((size_t)b * 1024 + row0 + 8) * 16;
    float* Pw = Qs + (w * 16) * AKL;

    for (int kt = 0; kt < 16; kt++) {
        __syncthreads();   // prev iter consumers done with Ks/Vs
        // load K,V tiles (tf32)
#pragma unroll
        for (int i = 0; i < 8; i++) {
            int e = tid + i * 128;
            int r = e >> 4, c = (e & 15) * 4;
            float4 kv = *(const float4*)(Kg + (size_t)(kt * 64 + r) * 64 + c);
            float* pk = Ks + r * AKL + c;
            pk[0] = to_tf32(kv.x); pk[1] = to_tf32(kv.y);
            pk[2] = to_tf32(kv.z); pk[3] = to_tf32(kv.w);
            float4 vv = *(const float4*)(Vg + (size_t)(kt * 64 + r) * 64 + c);
            float* pv = Vs + r * AVL + c;
            pv[0] = to_tf32(vv.x); pv[1] = to_tf32(vv.y);
            pv[2] = to_tf32(vv.z); pv[3] = to_tf32(vv.w);
        }
        __syncthreads();

        // S = Q K^T : per warp 16 x 64
        float s[8][4];
#pragma unroll
        for (int j = 0; j < 8; j++) {
            s[j][0] = 0.f; s[j][1] = 0.f; s[j][2] = 0.f; s[j][3] = 0.f;
#pragma unroll
            for (int ks = 0; ks < 8; ks++) {
                unsigned b0 = __float_as_uint(Ks[(j * 8 + g) * AKL + ks * 8 + t]);
                unsigned b1 = __float_as_uint(Ks[(j * 8 + g) * AKL + ks * 8 + t + 4]);
                mma8(s[j], qa[ks], b0, b1);
            }
        }

        // mask + scale
        const unsigned long long mb0 = g_maskbits[mb_base0 + kt];
        const unsigned long long mb1 = g_maskbits[mb_base1 + kt];
#pragma unroll
        for (int j = 0; j < 8; j++) {
            int c0 = j * 8 + t * 2;
            s[j][0] = ((mb0 >> c0) & 1ULL) ? s[j][0] * 0.125f : -1e30f;
            s[j][1] = ((mb0 >> (c0 + 1)) & 1ULL) ? s[j][1] * 0.125f : -1e30f;
            s[j][2] = ((mb1 >> c0) & 1ULL) ? s[j][2] * 0.125f : -1e30f;
            s[j][3] = ((mb1 >> (c0 + 1)) & 1ULL) ? s[j][3] * 0.125f : -1e30f;
        }

        // online softmax (rows row0 and row0+8), quad shfl reductions
        float rm0 = -1e30f, rm1 = -1e30f;
#pragma unroll
        for (int j = 0; j < 8; j++) {
            rm0 = fmaxf(rm0, fmaxf(s[j][0], s[j][1]));
            rm1 = fmaxf(rm1, fmaxf(s[j][2], s[j][3]));
        }
        rm0 = fmaxf(rm0, __shfl_xor_sync(0xffffffffu, rm0, 1));
        rm0 = fmaxf(rm0, __shfl_xor_sync(0xffffffffu, rm0, 2));
        rm1 = fmaxf(rm1, __shfl_xor_sync(0xffffffffu, rm1, 1));
        rm1 = fmaxf(rm1, __shfl_xor_sync(0xffffffffu, rm1, 2));

        float mn0 = fmaxf(mr0, rm0), mn1 = fmaxf(mr1, rm1);
        float al0 = __expf(mr0 - mn0), al1 = __expf(mr1 - mn1);
        float sum0 = 0.f, sum1 = 0.f;
#pragma unroll
        for (int j = 0; j < 8; j++) {
            float p0 = __expf(s[j][0] - mn0);
            float p1 = __expf(s[j][1] - mn0);
            float p2 = __expf(s[j][2] - mn1);
            float p3 = __expf(s[j][3] - mn1);
            s[j][0] = p0; s[j][1] = p1; s[j][2] = p2; s[j][3] = p3;
            sum0 += p0 + p1; sum1 += p2 + p3;
        }
        sum0 += __shfl_xor_sync(0xffffffffu, sum0, 1);
        sum0 += __shfl_xor_sync(0xffffffffu, sum0, 2);
        sum1 += __shfl_xor_sync(0xffffffffu, sum1, 1);
        sum1 += __shfl_xor_sync(0xffffffffu, sum1, 2);
        l0 = l0 * al0 + sum0; mr0 = mn0;
        l1 = l1 * al1 + sum1; mr1 = mn1;
#pragma unroll
        for (int j = 0; j < 8; j++) {
            o[j][0] *= al0; o[j][1] *= al0;
            o[j][2] *= al1; o[j][3] *= al1;
        }

        // P -> per-warp smem strip (C-layout -> A-layout hop), tf32
#pragma unroll
        for (int j = 0; j < 8; j++) {
            float2 p01 = make_float2(to_tf32(s[j][0]), to_tf32(s[j][1]));
            *(float2*)(Pw + g * AKL + j * 8 + t * 2) = p01;
            float2 p23 = make_float2(to_tf32(s[j][2]), to_tf32(s[j][3]));
            *(float2*)(Pw + (g + 8) * AKL + j * 8 + t * 2) = p23;
        }
        __syncwarp();

        // O += P V
#pragma unroll
        for (int ks = 0; ks < 8; ks++) {
            unsigned pa[4];
            pa[0] = __float_as_uint(Pw[g * AKL + ks * 8 + t]);
            pa[1] = __float_as_uint(Pw[(g + 8) * AKL + ks * 8 + t]);
            pa[2] = __float_as_uint(Pw[g * AKL + ks * 8 + t + 4]);
            pa[3] = __float_as_uint(Pw[(g + 8) * AKL + ks * 8 + t + 4]);
#pragma unroll
            for (int j = 0; j < 8; j++) {
                unsigned b0 = __float_as_uint(Vs[(ks * 8 + t) * AVL + j * 8 + g]);
                unsigned b1 = __float_as_uint(Vs[(ks * 8 + t + 4) * AVL + j * 8 + g]);
                mma8(o[j], pa, b0, b1);
            }
        }
        __syncwarp();   // P reads done before next iteration's P writes
    }

    // normalize + write out: row = lq*8 + b, col = h*64 + c
    const float inv0 = 1.f / l0, inv1 = 1.f / l1;
    const int lq0 = qt * 64 + w * 16 + g;
#pragma unroll
    for (int j = 0; j < 8; j++) {
        float2 o01 = make_float2(o[j][0] * inv0, o[j][1] * inv0);
        *(float2*)(g_attn + ((size_t)lq0 * 8 + b) * 1024 + h * 64 + j * 8 + t * 2) = o01;
        float2 o23 = make_float2(o[j][2] * inv1, o[j][3] * inv1);
        *(float2*)(g_attn + ((size_t)(lq0 + 8) * 8 + b) * 1024 + h * 64 + j * 8 + t * 2) = o23;
    }
}

// ---------------------------------------------------------------------------
// Final bias add: out[m, :] += bo
// ---------------------------------------------------------------------------
__global__ __launch_bounds__(256) void bias_add_kernel(float* __restrict__ out,
                                                       const float* __restrict__ bo)
{
    const int m = blockIdx.x;
    const int c = threadIdx.x * 4;
    float4 o = *(float4*)(out + (size_t)m * 1024 + c);
    float4 bb = *(const float4*)(bo + c);
    o.x += bb.x; o.y += bb.y; o.z += bb.z; o.w += bb.w;
    *(float4*)(out + (size_t)m * 1024 + c) = o;
}

// ---------------------------------------------------------------------------
// Launch
// ---------------------------------------------------------------------------
extern "C" void kernel_launch(void* const* d_in, const int* in_sizes, int n_in,
                              void* d_out, int out_size)
{
    const float* hs   = (const float*)d_in[0];
    const float* rpe  = (const float*)d_in[1];
    const void* maskp = d_in[2];
    const float* Wqkv = (const float*)d_in[3];
    const float* bqkv = (const float*)d_in[4];
    const float* Wo   = (const float*)d_in[5];
    const float* bo   = (const float*)d_in[6];
    float* out        = (float*)d_out;

    float *qkv_p, *attn_p;
    cudaGetSymbolAddress((void**)&qkv_p, g_qkv);
    cudaGetSymbolAddress((void**)&attn_p, g_attn);

    // Stage 0: mask canonicalization -> bit-packed
    detect_mask_mode_kernel<<<1, 32>>>((const unsigned char*)maskp);
    convert_mask_bits_kernel<<<131072 / 256, 256>>>(maskp);

    const int gemm_smem = 4 * GSTAGE * sizeof(float);   // 73728
    cudaFuncSetAttribute(gemm_nt_tf32,
                         cudaFuncAttributeMaxDynamicSharedMemorySize, gemm_smem);

    // Stage 1: QKV projection (bias deferred to rope)
    {
        dim3 grid(3072 / 128, 8192 / 128);
        gemm_nt_tf32<<<grid, 256, gemm_smem>>>(hs, Wqkv, qkv_p, 8192, 3072, 1024);
    }

    // Stage 2: RoPE + bqkv + transpose
    rope_bias_transpose_kernel<<<8192, 256>>>(rpe, bqkv);

    // Stage 3: attention
    {
        const int smem = (2 * 64 * AKL + 64 * AVL) * sizeof(float);  // 53248
        cudaFuncSetAttribute(attn_tf32_reg,
                             cudaFuncAttributeMaxDynamicSharedMemorySize, smem);
        dim3 grid(128, 16);
        attn_tf32_reg<<<grid, 128, smem>>>();
    }

    // Stage 4: output projection + bias
    {
        dim3 grid(1024 / 128, 8192 / 128);
        gemm_nt_tf32<<<grid, 256, gemm_smem>>>(attn_p, Wo, out, 8192, 1024, 1024);
        bias_add_kernel<<<8192, 256>>>(out, bo);
    }
}

// round 6
// speedup vs baseline: 2.1408x; 1.2194x over previous
#include <cuda_runtime.h>
#include <mma.h>

using namespace nvcuda;

// ---------------------------------------------------------------------------
// VisionSdpaAttention — TF32 tensor-core v3
//   pre-rounded tf32 operands (no CVT in hot loops), parallel mask detect,
//   cp.async double-buffered GEMM + attention.
// ---------------------------------------------------------------------------

__device__ float g_hs[8388608];               // tf32-rounded hidden_states
__device__ float g_wqkv[3145728];             // tf32-rounded Wqkv
__device__ float g_wo[1048576];               // tf32-rounded Wo
__device__ float g_qkv[25165824];             // (L*B, 3C)
__device__ float g_q[8388608];                // (B,H,L,D) tf32-rounded
__device__ float g_k[8388608];
__device__ float g_v[8388608];
__device__ float g_attn[8388608];             // (L*B, C) tf32-rounded
__device__ unsigned long long g_maskbits[131072];  // [B][L][16 chunks of 64]
__device__ int g_mask_mode;

__device__ __forceinline__ float to_tf32(float x) {
    unsigned int u;
    asm("cvt.rna.tf32.f32 %0, %1;" : "=r"(u) : "f"(x));
    return __uint_as_float(u);
}

__device__ __forceinline__ void cp_async16(void* sptr, const void* gptr) {
    unsigned s = (unsigned)__cvta_generic_to_shared(sptr);
    asm volatile("cp.async.cg.shared.global [%0], [%1], 16;" :: "r"(s), "l"(gptr));
}
__device__ __forceinline__ void cp_commit() {
    asm volatile("cp.async.commit_group;");
}

// mma.sync m16n8k8 tf32: D = A(16x8) * B(8x8) + D
__device__ __forceinline__ void mma8(float* c, const unsigned* a, unsigned b0, unsigned b1) {
    asm volatile(
        "mma.sync.aligned.m16n8k8.row.col.f32.tf32.tf32.f32 "
        "{%0,%1,%2,%3},{%4,%5,%6,%7},{%8,%9},{%0,%1,%2,%3};"
        : "+f"(c[0]), "+f"(c[1]), "+f"(c[2]), "+f"(c[3])
        : "r"(a[0]), "r"(a[1]), "r"(a[2]), "r"(a[3]), "r"(b0), "r"(b1));
}

// ---------------------------------------------------------------------------
// tf32 rounding copy (grid-stride float4)
// ---------------------------------------------------------------------------
__global__ __launch_bounds__(256) void tf32_round_kernel(
    float* __restrict__ dst, const float* __restrict__ src, int n4)
{
    int i = blockIdx.x * 256 + threadIdx.x;
    if (i >= n4) return;
    float4 v = *((const float4*)src + i);
    v.x = to_tf32(v.x); v.y = to_tf32(v.y);
    v.z = to_tf32(v.z); v.w = to_tf32(v.w);
    *((float4*)dst + i) = v;
}

// ---------------------------------------------------------------------------
// Mask dtype detection (parallel) + bitpack
// ---------------------------------------------------------------------------
__global__ void detect_mask_mode_kernel(const unsigned char* __restrict__ m)
{
    __shared__ int s1, s23;
    const int tid = threadIdx.x;
    if (tid == 0) { s1 = 0; s23 = 0; }
    __syncthreads();
    bool o1 = false, o23 = false;
    for (int i = tid * 4; i < 16384; i += 1024) {
        if (m[i + 1] != 0) o1 = true;
        if (m[i + 2] != 0 || m[i + 3] != 0) o23 = true;
    }
    if (o1) atomicOr(&s1, 1);
    if (o23) atomicOr(&s23, 1);
    __syncthreads();
    if (tid == 0) g_mask_mode = s1 ? 0 : (s23 ? 2 : 1);
}

__global__ __launch_bounds__(256) void convert_mask_bits_kernel(const void* __restrict__ mp)
{
    const int idx = blockIdx.x * 256 + threadIdx.x;   // 0..131071
    const int mode = g_mask_mode;
    unsigned long long bits = 0ULL;
    const size_t base = (size_t)idx * 64;
    if (mode == 0) {
        const uint4* p = (const uint4*)((const unsigned char*)mp + base);
#pragma unroll
        for (int wrd = 0; wrd < 4; wrd++) {
            uint4 v = p[wrd];
            unsigned ws[4] = {v.x, v.y, v.z, v.w};
#pragma unroll
            for (int q = 0; q < 4; q++)
#pragma unroll
                for (int by = 0; by < 4; by++)
                    if ((ws[q] >> (by * 8)) & 0xffu)
                        bits |= 1ULL << (wrd * 16 + q * 4 + by);
        }
    } else if (mode == 1) {
        const int* p = (const int*)mp + base;
#pragma unroll 8
        for (int j = 0; j < 64; j++)
            if (p[j] != 0) bits |= 1ULL << j;
    } else {
        const float* p = (const float*)mp + base;
#pragma unroll 8
        for (int j = 0; j < 64; j++)
            if (p[j] != 0.0f) bits |= 1ULL << j;
    }
    g_maskbits[idx] = bits;
}

// ---------------------------------------------------------------------------
// TF32 WMMA GEMM NT (no bias, pre-rounded inputs): C = A * B^T
// BM=BN=128, BK=32, 256 threads, cp.async double buffer, direct frag stores.
// ---------------------------------------------------------------------------
#define GLDA 36
#define GSTAGE (128 * GLDA)

__global__ __launch_bounds__(256) void gemm_nt_tf32(
    const float* __restrict__ A, const float* __restrict__ B,
    float* __restrict__ C, int M, int N, int K)
{
    extern __shared__ float sg[];
    float* Asb[2] = { sg,               sg + GSTAGE };
    float* Bsb[2] = { sg + 2 * GSTAGE,  sg + 3 * GSTAGE };

    const int bm = blockIdx.y * 128;
    const int bn = blockIdx.x * 128;
    const int tid = threadIdx.x;
    const int wid = tid >> 5;
    const int warpM = wid & 3;
    const int warpN = wid >> 2;

    wmma::fragment<wmma::accumulator, 16, 16, 8, float> acc[2][4];
#pragma unroll
    for (int i = 0; i < 2; i++)
#pragma unroll
        for (int j = 0; j < 4; j++) wmma::fill_fragment(acc[i][j], 0.0f);

    const int nk = K / 32;

    // prologue: stage 0
#pragma unroll
    for (int i = 0; i < 4; i++) {
        int e = tid + i * 256;
        int r = e >> 3, c = (e & 7) * 4;
        cp_async16(Asb[0] + r * GLDA + c, A + (size_t)(bm + r) * K + c);
        cp_async16(Bsb[0] + r * GLDA + c, B + (size_t)(bn + r) * K + c);
    }
    cp_commit();

    for (int it = 0; it < nk; it++) {
        if (it + 1 < nk) {
            const int k0n = (it + 1) * 32;
            float* An = Asb[(it + 1) & 1];
            float* Bn = Bsb[(it + 1) & 1];
#pragma unroll
            for (int i = 0; i < 4; i++) {
                int e = tid + i * 256;
                int r = e >> 3, c = (e & 7) * 4;
                cp_async16(An + r * GLDA + c, A + (size_t)(bm + r) * K + k0n + c);
                cp_async16(Bn + r * GLDA + c, B + (size_t)(bn + r) * K + k0n + c);
            }
            cp_commit();
            asm volatile("cp.async.wait_group 1;");
        } else {
            asm volatile("cp.async.wait_group 0;");
        }
        __syncthreads();

        const float* As = Asb[it & 1];
        const float* Bs = Bsb[it & 1];
#pragma unroll
        for (int ks = 0; ks < 4; ks++) {
            wmma::fragment<wmma::matrix_a, 16, 16, 8, wmma::precision::tf32, wmma::row_major> af[2];
            wmma::fragment<wmma::matrix_b, 16, 16, 8, wmma::precision::tf32, wmma::col_major> bf[4];
#pragma unroll
            for (int i = 0; i < 2; i++)
                wmma::load_matrix_sync(af[i], As + (warpM * 32 + i * 16) * GLDA + ks * 8, GLDA);
#pragma unroll
            for (int j = 0; j < 4; j++)
                wmma::load_matrix_sync(bf[j], Bs + (warpN * 64 + j * 16) * GLDA + ks * 8, GLDA);
#pragma unroll
            for (int i = 0; i < 2; i++)
#pragma unroll
                for (int j = 0; j < 4; j++)
                    wmma::mma_sync(acc[i][j], af[i], bf[j], acc[i][j]);
        }
        __syncthreads();
    }

#pragma unroll
    for (int i = 0; i < 2; i++)
#pragma unroll
        for (int j = 0; j < 4; j++)
            wmma::store_matrix_sync(
                C + (size_t)(bm + warpM * 32 + i * 16) * N + bn + warpN * 64 + j * 16,
                acc[i][j], N, wmma::mem_row_major);
}

// ---------------------------------------------------------------------------
// RoPE + bias + transpose, tf32-rounded stores
// ---------------------------------------------------------------------------
__global__ __launch_bounds__(256) void rope_bias_transpose_kernel(
    const float* __restrict__ rpe, const float* __restrict__ bq)
{
    __shared__ float cs[32], sn[32];
    const int m = blockIdx.x;   // l*8 + b
    const int l = m >> 3;
    const int b = m & 7;
    const int tid = threadIdx.x;
    if (tid < 32) {
        float a = rpe[l * 32 + tid];
        cs[tid] = cosf(a);
        sn[tid] = sinf(a);
    }
    __syncthreads();
    const float* src = g_qkv + (size_t)m * 3072;
    for (int r = tid; r < 3072; r += 256) {
        int which = r >> 10;
        int hh = (r >> 6) & 15;
        int d = r & 63;
        float x = src[r] + bq[r];
        float val;
        if (which < 2) {
            float xp = src[r ^ 1] + bq[r ^ 1];
            float c = cs[d & 31];
            float s = sn[d & 31];
            val = x * c + ((d & 1) ? xp : -xp) * s;
        } else {
            val = x;
        }
        float* dst = (which == 0) ? g_q : (which == 1) ? g_k : g_v;
        dst[(((size_t)(b * 16 + hh)) * 1024 + l) * 64 + d] = to_tf32(val);
    }
}

// ---------------------------------------------------------------------------
// Flash attention, register-resident FA2, mma.m16n8k8 tf32.
// grid (128 heads, 16 q-tiles), 128 threads (4 warps).
// Pre-rounded q/k/v; cp.async double-buffered K/V tiles.
// smem: Qs(=P) [64][68], Ks[2] [64][68], Vs[2] [64][72]  = 89088 B
// ---------------------------------------------------------------------------
#define AKL 68
#define AVL 72
#define KSTG (64 * AKL)
#define VSTG (64 * AVL)

__global__ __launch_bounds__(128) void attn_tf32_reg()
{
    extern __shared__ float sm[];
    float* Qs = sm;                        // 64*68 (doubles as P strips)
    float* Ksb[2] = { sm + KSTG,           sm + 2 * KSTG };
    float* Vsb[2] = { sm + 3 * KSTG,       sm + 3 * KSTG + VSTG };

    const int bh = blockIdx.x;   // b*16 + h
    const int b = bh >> 4;
    const int h = bh & 15;
    const int qt = blockIdx.y;
    const int tid = threadIdx.x;
    const int w = tid >> 5;
    const int lane = tid & 31;
    const int g = lane >> 2;
    const int t = lane & 3;

    const float* Kg = g_k + (size_t)bh * 1024 * 64;
    const float* Vg = g_v + (size_t)bh * 1024 * 64;

    // prologue: kt=0 K/V via cp.async
#pragma unroll
    for (int i = 0; i < 8; i++) {
        int e = tid + i * 128;
        int r = e >> 4, c = (e & 15) * 4;
        cp_async16(Ksb[0] + r * AKL + c, Kg + (size_t)r * 64 + c);
        cp_async16(Vsb[0] + r * AVL + c, Vg + (size_t)r * 64 + c);
    }
    cp_commit();

    // load Q tile -> smem (already tf32)
    {
        const float* Qg = g_q + ((size_t)bh * 1024 + qt * 64) * 64;
#pragma unroll
        for (int i = 0; i < 8; i++) {
            int e = tid + i * 128;
            int r = e >> 4, c = (e & 15) * 4;
            float4 v = *(const float4*)(Qg + r * 64 + c);
            *(float4*)(Qs + r * AKL + c) = v;
        }
    }
    __syncthreads();

    // Q A-fragments register-resident
    unsigned qa[8][4];
    {
        const float* Qw = Qs + (w * 16) * AKL;
#pragma unroll
        for (int ks = 0; ks < 8; ks++) {
            qa[ks][0] = __float_as_uint(Qw[g * AKL + ks * 8 + t]);
            qa[ks][1] = __float_as_uint(Qw[(g + 8) * AKL + ks * 8 + t]);
            qa[ks][2] = __float_as_uint(Qw[g * AKL + ks * 8 + t + 4]);
            qa[ks][3] = __float_as_uint(Qw[(g + 8) * AKL + ks * 8 + t + 4]);
        }
    }
    __syncthreads();   // Qs now free to act as P

    float o[8][4];
#pragma unroll
    for (int j = 0; j < 8; j++) { o[j][0] = 0.f; o[j][1] = 0.f; o[j][2] = 0.f; o[j][3] = 0.f; }
    float mr0 = -1e30f, mr1 = -1e30f, l0 = 0.f, l1 = 0.f;

    const int row0 = qt * 64 + w * 16 + g;
    const size_t mb_base0 = ((size_t)b * 1024 + row0) * 16;
    const size_t mb_base1 = ((size_t)b * 1024 + row0 + 8) * 16;
    float* Pw = Qs + (w * 16) * AKL;

    for (int kt = 0; kt < 16; kt++) {
        // issue next K/V, wait current
        if (kt + 1 < 16) {
            float* Kn = Ksb[(kt + 1) & 1];
            float* Vn = Vsb[(kt + 1) & 1];
            const size_t off = (size_t)(kt + 1) * 64 * 64;
#pragma unroll
            for (int i = 0; i < 8; i++) {
                int e = tid + i * 128;
                int r = e >> 4, c = (e & 15) * 4;
                cp_async16(Kn + r * AKL + c, Kg + off + (size_t)r * 64 + c);
                cp_async16(Vn + r * AVL + c, Vg + off + (size_t)r * 64 + c);
            }
            cp_commit();
            asm volatile("cp.async.wait_group 1;");
        } else {
            asm volatile("cp.async.wait_group 0;");
        }
        __syncthreads();

        const float* Ks = Ksb[kt & 1];
        const float* Vs = Vsb[kt & 1];

        // S = Q K^T : per warp 16 x 64
        float s[8][4];
#pragma unroll
        for (int j = 0; j < 8; j++) {
            s[j][0] = 0.f; s[j][1] = 0.f; s[j][2] = 0.f; s[j][3] = 0.f;
#pragma unroll
            for (int ks = 0; ks < 8; ks++) {
                unsigned b0 = __float_as_uint(Ks[(j * 8 + g) * AKL + ks * 8 + t]);
                unsigned b1 = __float_as_uint(Ks[(j * 8 + g) * AKL + ks * 8 + t + 4]);
                mma8(s[j], qa[ks], b0, b1);
            }
        }

        // mask + scale
        const unsigned long long mb0 = g_maskbits[mb_base0 + kt];
        const unsigned long long mb1 = g_maskbits[mb_base1 + kt];
#pragma unroll
        for (int j = 0; j < 8; j++) {
            int c0 = j * 8 + t * 2;
            s[j][0] = ((mb0 >> c0) & 1ULL) ? s[j][0] * 0.125f : -1e30f;
            s[j][1] = ((mb0 >> (c0 + 1)) & 1ULL) ? s[j][1] * 0.125f : -1e30f;
            s[j][2] = ((mb1 >> c0) & 1ULL) ? s[j][2] * 0.125f : -1e30f;
            s[j][3] = ((mb1 >> (c0 + 1)) & 1ULL) ? s[j][3] * 0.125f : -1e30f;
        }

        // online softmax
        float rm0 = -1e30f, rm1 = -1e30f;
#pragma unroll
        for (int j = 0; j < 8; j++) {
            rm0 = fmaxf(rm0, fmaxf(s[j][0], s[j][1]));
            rm1 = fmaxf(rm1, fmaxf(s[j][2], s[j][3]));
        }
        rm0 = fmaxf(rm0, __shfl_xor_sync(0xffffffffu, rm0, 1));
        rm0 = fmaxf(rm0, __shfl_xor_sync(0xffffffffu, rm0, 2));
        rm1 = fmaxf(rm1, __shfl_xor_sync(0xffffffffu, rm1, 1));
        rm1 = fmaxf(rm1, __shfl_xor_sync(0xffffffffu, rm1, 2));

        float mn0 = fmaxf(mr0, rm0), mn1 = fmaxf(mr1, rm1);
        float al0 = __expf(mr0 - mn0), al1 = __expf(mr1 - mn1);
        float sum0 = 0.f, sum1 = 0.f;
#pragma unroll
        for (int j = 0; j < 8; j++) {
            float p0 = __expf(s[j][0] - mn0);
            float p1 = __expf(s[j][1] - mn0);
            float p2 = __expf(s[j][2] - mn1);
            float p3 = __expf(s[j][3] - mn1);
            s[j][0] = p0; s[j][1] = p1; s[j][2] = p2; s[j][3] = p3;
            sum0 += p0 + p1; sum1 += p2 + p3;
        }
        sum0 += __shfl_xor_sync(0xffffffffu, sum0, 1);
        sum0 += __shfl_xor_sync(0xffffffffu, sum0, 2);
        sum1 += __shfl_xor_sync(0xffffffffu, sum1, 1);
        sum1 += __shfl_xor_sync(0xffffffffu, sum1, 2);
        l0 = l0 * al0 + sum0; mr0 = mn0;
        l1 = l1 * al1 + sum1; mr1 = mn1;
#pragma unroll
        for (int j = 0; j < 8; j++) {
            o[j][0] *= al0; o[j][1] *= al0;
            o[j][2] *= al1; o[j][3] *= al1;
        }

        // P -> per-warp smem strip (tf32)
#pragma unroll
        for (int j = 0; j < 8; j++) {
            float2 p01 = make_float2(to_tf32(s[j][0]), to_tf32(s[j][1]));
            *(float2*)(Pw + g * AKL + j * 8 + t * 2) = p01;
            float2 p23 = make_float2(to_tf32(s[j][2]), to_tf32(s[j][3]));
            *(float2*)(Pw + (g + 8) * AKL + j * 8 + t * 2) = p23;
        }
        __syncwarp();

        // O += P V
#pragma unroll
        for (int ks = 0; ks < 8; ks++) {
            unsigned pa[4];
            pa[0] = __float_as_uint(Pw[g * AKL + ks * 8 + t]);
            pa[1] = __float_as_uint(Pw[(g + 8) * AKL + ks * 8 + t]);
            pa[2] = __float_as_uint(Pw[g * AKL + ks * 8 + t + 4]);
            pa[3] = __float_as_uint(Pw[(g + 8) * AKL + ks * 8 + t + 4]);
#pragma unroll
            for (int j = 0; j < 8; j++) {
                unsigned b0 = __float_as_uint(Vs[(ks * 8 + t) * AVL + j * 8 + g]);
                unsigned b1 = __float_as_uint(Vs[(ks * 8 + t + 4) * AVL + j * 8 + g]);
                mma8(o[j], pa, b0, b1);
            }
        }
        __syncthreads();   // all reads of Ks/Vs/P done before next iteration
    }

    // normalize + write out (tf32-rounded for gemm2)
    const float inv0 = 1.f / l0, inv1 = 1.f / l1;
    const int lq0 = qt * 64 + w * 16 + g;
#pragma unroll
    for (int j = 0; j < 8; j++) {
        float2 o01 = make_float2(to_tf32(o[j][0] * inv0), to_tf32(o[j][1] * inv0));
        *(float2*)(g_attn + ((size_t)lq0 * 8 + b) * 1024 + h * 64 + j * 8 + t * 2) = o01;
        float2 o23 = make_float2(to_tf32(o[j][2] * inv1), to_tf32(o[j][3] * inv1));
        *(float2*)(g_attn + ((size_t)(lq0 + 8) * 8 + b) * 1024 + h * 64 + j * 8 + t * 2) = o23;
    }
}

// ---------------------------------------------------------------------------
// Final bias add
// ---------------------------------------------------------------------------
__global__ __launch_bounds__(256) void bias_add_kernel(float* __restrict__ out,
                                                       const float* __restrict__ bo)
{
    const int m = blockIdx.x;
    const int c = threadIdx.x * 4;
    float4 o = *(float4*)(out + (size_t)m * 1024 + c);
    float4 bb = *(const float4*)(bo + c);
    o.x += bb.x; o.y += bb.y; o.z += bb.z; o.w += bb.w;
    *(float4*)(out + (size_t)m * 1024 + c) = o;
}

// ---------------------------------------------------------------------------
// Launch
// ---------------------------------------------------------------------------
extern "C" void kernel_launch(void* const* d_in, const int* in_sizes, int n_in,
                              void* d_out, int out_size)
{
    const float* hs   = (const float*)d_in[0];
    const float* rpe  = (const float*)d_in[1];
    const void* maskp = d_in[2];
    const float* Wqkv = (const float*)d_in[3];
    const float* bqkv = (const float*)d_in[4];
    const float* Wo   = (const float*)d_in[5];
    const float* bo   = (const float*)d_in[6];
    float* out        = (float*)d_out;

    float *hs_p, *wqkv_p, *wo_p, *qkv_p, *attn_p;
    cudaGetSymbolAddress((void**)&hs_p, g_hs);
    cudaGetSymbolAddress((void**)&wqkv_p, g_wqkv);
    cudaGetSymbolAddress((void**)&wo_p, g_wo);
    cudaGetSymbolAddress((void**)&qkv_p, g_qkv);
    cudaGetSymbolAddress((void**)&attn_p, g_attn);

    // Stage 0: mask canonicalization + operand pre-rounding
    detect_mask_mode_kernel<<<1, 256>>>((const unsigned char*)maskp);
    convert_mask_bits_kernel<<<131072 / 256, 256>>>(maskp);
    tf32_round_kernel<<<(8388608 / 4) / 256, 256>>>(hs_p, hs, 8388608 / 4);
    tf32_round_kernel<<<(3145728 / 4) / 256, 256>>>(wqkv_p, Wqkv, 3145728 / 4);
    tf32_round_kernel<<<(1048576 / 4) / 256, 256>>>(wo_p, Wo, 1048576 / 4);

    const int gemm_smem = 4 * GSTAGE * sizeof(float);   // 73728
    cudaFuncSetAttribute(gemm_nt_tf32,
                         cudaFuncAttributeMaxDynamicSharedMemorySize, gemm_smem);

    // Stage 1: QKV projection (bias deferred to rope)
    {
        dim3 grid(3072 / 128, 8192 / 128);
        gemm_nt_tf32<<<grid, 256, gemm_smem>>>(hs_p, wqkv_p, qkv_p, 8192, 3072, 1024);
    }

    // Stage 2: RoPE + bqkv + transpose (tf32-rounded q/k/v)
    rope_bias_transpose_kernel<<<8192, 256>>>(rpe, bqkv);

    // Stage 3: attention
    {
        const int smem = (3 * KSTG + 2 * VSTG) * sizeof(float);  // 89088
        cudaFuncSetAttribute(attn_tf32_reg,
                             cudaFuncAttributeMaxDynamicSharedMemorySize, smem);
        dim3 grid(128, 16);
        attn_tf32_reg<<<grid, 128, smem>>>();
    }

    // Stage 4: output projection + bias
    {
        dim3 grid(1024 / 128, 8192 / 128);
        gemm_nt_tf32<<<grid, 256, gemm_smem>>>(attn_p, wo_p, out, 8192, 1024, 1024);
        bias_add_kernel<<<8192, 256>>>(out, bo);
    }
}

// round 7
// speedup vs baseline: 2.2361x; 1.0445x over previous
#include <cuda_runtime.h>
#include <mma.h>

using namespace nvcuda;

// ---------------------------------------------------------------------------
// VisionSdpaAttention — TF32 tensor-core v4
//   64x64 warp-tile GEMM (block 128x256), 32-row-per-warp flash attention.
// ---------------------------------------------------------------------------

__device__ float g_hs[8388608];               // tf32-rounded hidden_states
__device__ float g_wqkv[3145728];             // tf32-rounded Wqkv
__device__ float g_wo[1048576];               // tf32-rounded Wo
__device__ float g_qkv[25165824];             // (L*B, 3C)
__device__ float g_q[8388608];                // (B,H,L,D) tf32-rounded
__device__ float g_k[8388608];
__device__ float g_v[8388608];
__device__ float g_attn[8388608];             // (L*B, C) tf32-rounded
__device__ unsigned long long g_maskbits[131072];  // [B][L][16 chunks of 64]
__device__ int g_mask_mode;

__device__ __forceinline__ float to_tf32(float x) {
    unsigned int u;
    asm("cvt.rna.tf32.f32 %0, %1;" : "=r"(u) : "f"(x));
    return __uint_as_float(u);
}

__device__ __forceinline__ void cp_async16(void* sptr, const void* gptr) {
    unsigned s = (unsigned)__cvta_generic_to_shared(sptr);
    asm volatile("cp.async.cg.shared.global [%0], [%1], 16;" :: "r"(s), "l"(gptr));
}
__device__ __forceinline__ void cp_commit() {
    asm volatile("cp.async.commit_group;");
}

// mma.sync m16n8k8 tf32: D = A(16x8) * B(8x8) + D
__device__ __forceinline__ void mma8(float* c, const unsigned* a, unsigned b0, unsigned b1) {
    asm volatile(
        "mma.sync.aligned.m16n8k8.row.col.f32.tf32.tf32.f32 "
        "{%0,%1,%2,%3},{%4,%5,%6,%7},{%8,%9},{%0,%1,%2,%3};"
        : "+f"(c[0]), "+f"(c[1]), "+f"(c[2]), "+f"(c[3])
        : "r"(a[0]), "r"(a[1]), "r"(a[2]), "r"(a[3]), "r"(b0), "r"(b1));
}

// ---------------------------------------------------------------------------
// tf32 rounding copy
// ---------------------------------------------------------------------------
__global__ __launch_bounds__(256) void tf32_round_kernel(
    float* __restrict__ dst, const float* __restrict__ src, int n4)
{
    int i = blockIdx.x * 256 + threadIdx.x;
    if (i >= n4) return;
    float4 v = *((const float4*)src + i);
    v.x = to_tf32(v.x); v.y = to_tf32(v.y);
    v.z = to_tf32(v.z); v.w = to_tf32(v.w);
    *((float4*)dst + i) = v;
}

// ---------------------------------------------------------------------------
// Mask dtype detection (parallel) + bitpack
// ---------------------------------------------------------------------------
__global__ void detect_mask_mode_kernel(const unsigned char* __restrict__ m)
{
    __shared__ int s1, s23;
    const int tid = threadIdx.x;
    if (tid == 0) { s1 = 0; s23 = 0; }
    __syncthreads();
    bool o1 = false, o23 = false;
    for (int i = tid * 4; i < 16384; i += 1024) {
        if (m[i + 1] != 0) o1 = true;
        if (m[i + 2] != 0 || m[i + 3] != 0) o23 = true;
    }
    if (o1) atomicOr(&s1, 1);
    if (o23) atomicOr(&s23, 1);
    __syncthreads();
    if (tid == 0) g_mask_mode = s1 ? 0 : (s23 ? 2 : 1);
}

__global__ __launch_bounds__(256) void convert_mask_bits_kernel(const void* __restrict__ mp)
{
    const int idx = blockIdx.x * 256 + threadIdx.x;   // 0..131071
    const int mode = g_mask_mode;
    unsigned long long bits = 0ULL;
    const size_t base = (size_t)idx * 64;
    if (mode == 0) {
        const uint4* p = (const uint4*)((const unsigned char*)mp + base);
#pragma unroll
        for (int wrd = 0; wrd < 4; wrd++) {
            uint4 v = p[wrd];
            unsigned ws[4] = {v.x, v.y, v.z, v.w};
#pragma unroll
            for (int q = 0; q < 4; q++)
#pragma unroll
                for (int by = 0; by < 4; by++)
                    if ((ws[q] >> (by * 8)) & 0xffu)
                        bits |= 1ULL << (wrd * 16 + q * 4 + by);
        }
    } else if (mode == 1) {
        const int* p = (const int*)mp + base;
#pragma unroll 8
        for (int j = 0; j < 64; j++)
            if (p[j] != 0) bits |= 1ULL << j;
    } else {
        const float* p = (const float*)mp + base;
#pragma unroll 8
        for (int j = 0; j < 64; j++)
            if (p[j] != 0.0f) bits |= 1ULL << j;
    }
    g_maskbits[idx] = bits;
}

// ---------------------------------------------------------------------------
// TF32 WMMA GEMM NT: C = A * B^T   (pre-rounded inputs, no bias)
// BM=128, BN=256, BK=32; 256 threads = 8 warps (2 M x 4 N), warp tile 64x64.
// cp.async double buffer. smem: 2*(128+256)*36*4 = 110.6 KB
// ---------------------------------------------------------------------------
#define GLDA 36
#define ASTG (128 * GLDA)
#define BSTG (256 * GLDA)

__global__ __launch_bounds__(256) void gemm_nt_tf32(
    const float* __restrict__ A, const float* __restrict__ B,
    float* __restrict__ C, int M, int N, int K)
{
    extern __shared__ float sg[];
    float* Asb[2] = { sg,                       sg + ASTG };
    float* Bsb[2] = { sg + 2 * ASTG,            sg + 2 * ASTG + BSTG };

    const int bm = blockIdx.y * 128;
    const int bn = blockIdx.x * 256;
    const int tid = threadIdx.x;
    const int wid = tid >> 5;
    const int warpM = wid & 1;       // 0..1 -> rows warpM*64
    const int warpN = wid >> 1;      // 0..3 -> cols warpN*64

    wmma::fragment<wmma::accumulator, 16, 16, 8, float> acc[4][4];
#pragma unroll
    for (int i = 0; i < 4; i++)
#pragma unroll
        for (int j = 0; j < 4; j++) wmma::fill_fragment(acc[i][j], 0.0f);

    const int nk = K / 32;

    // prologue: stage 0
#pragma unroll
    for (int i = 0; i < 4; i++) {          // A: 1024 float4 / 256 thr
        int e = tid + i * 256;
        int r = e >> 3, c = (e & 7) * 4;
        cp_async16(Asb[0] + r * GLDA + c, A + (size_t)(bm + r) * K + c);
    }
#pragma unroll
    for (int i = 0; i < 8; i++) {          // B: 2048 float4 / 256 thr
        int e = tid + i * 256;
        int r = e >> 3, c = (e & 7) * 4;
        cp_async16(Bsb[0] + r * GLDA + c, B + (size_t)(bn + r) * K + c);
    }
    cp_commit();

    for (int it = 0; it < nk; it++) {
        if (it + 1 < nk) {
            const int k0n = (it + 1) * 32;
            float* An = Asb[(it + 1) & 1];
            float* Bn = Bsb[(it + 1) & 1];
#pragma unroll
            for (int i = 0; i < 4; i++) {
                int e = tid + i * 256;
                int r = e >> 3, c = (e & 7) * 4;
                cp_async16(An + r * GLDA + c, A + (size_t)(bm + r) * K + k0n + c);
            }
#pragma unroll
            for (int i = 0; i < 8; i++) {
                int e = tid + i * 256;
                int r = e >> 3, c = (e & 7) * 4;
                cp_async16(Bn + r * GLDA + c, B + (size_t)(bn + r) * K + k0n + c);
            }
            cp_commit();
            asm volatile("cp.async.wait_group 1;");
        } else {
            asm volatile("cp.async.wait_group 0;");
        }
        __syncthreads();

        const float* As = Asb[it & 1];
        const float* Bs = Bsb[it & 1];
#pragma unroll
        for (int ks = 0; ks < 4; ks++) {
            wmma::fragment<wmma::matrix_a, 16, 16, 8, wmma::precision::tf32, wmma::row_major> af[4];
            wmma::fragment<wmma::matrix_b, 16, 16, 8, wmma::precision::tf32, wmma::col_major> bf[4];
#pragma unroll
            for (int i = 0; i < 4; i++)
                wmma::load_matrix_sync(af[i], As + (warpM * 64 + i * 16) * GLDA + ks * 8, GLDA);
#pragma unroll
            for (int j = 0; j < 4; j++)
                wmma::load_matrix_sync(bf[j], Bs + (warpN * 64 + j * 16) * GLDA + ks * 8, GLDA);
#pragma unroll
            for (int i = 0; i < 4; i++)
#pragma unroll
                for (int j = 0; j < 4; j++)
                    wmma::mma_sync(acc[i][j], af[i], bf[j], acc[i][j]);
        }
        __syncthreads();
    }

#pragma unroll
    for (int i = 0; i < 4; i++)
#pragma unroll
        for (int j = 0; j < 4; j++)
            wmma::store_matrix_sync(
                C + (size_t)(bm + warpM * 64 + i * 16) * N + bn + warpN * 64 + j * 16,
                acc[i][j], N, wmma::mem_row_major);
}

// ---------------------------------------------------------------------------
// RoPE + bias + transpose, tf32-rounded stores
// ---------------------------------------------------------------------------
__global__ __launch_bounds__(256) void rope_bias_transpose_kernel(
    const float* __restrict__ rpe, const float* __restrict__ bq)
{
    __shared__ float cs[32], sn[32];
    const int m = blockIdx.x;   // l*8 + b
    const int l = m >> 3;
    const int b = m & 7;
    const int tid = threadIdx.x;
    if (tid < 32) {
        float a = rpe[l * 32 + tid];
        cs[tid] = cosf(a);
        sn[tid] = sinf(a);
    }
    __syncthreads();
    const float* src = g_qkv + (size_t)m * 3072;
    for (int r = tid; r < 3072; r += 256) {
        int which = r >> 10;
        int hh = (r >> 6) & 15;
        int d = r & 63;
        float x = src[r] + bq[r];
        float val;
        if (which < 2) {
            float xp = src[r ^ 1] + bq[r ^ 1];
            float c = cs[d & 31];
            float s = sn[d & 31];
            val = x * c + ((d & 1) ? xp : -xp) * s;
        } else {
            val = x;
        }
        float* dst = (which == 0) ? g_q : (which == 1) ? g_k : g_v;
        dst[(((size_t)(b * 16 + hh)) * 1024 + l) * 64 + d] = to_tf32(val);
    }
}

// ---------------------------------------------------------------------------
// Flash attention, 32 Q rows per warp. grid (128 heads, 8 q-tiles of 128),
// 128 threads (4 warps). K/V tiles 64 rows, cp.async double-buffered.
// Each warp: 2 row-fragments (rf) of 16 rows; K/V frags loaded once per
// (j,ks) and reused for both rf -> smem traffic per MAC halved.
// smem: Qs[128][68] (doubles as P strips) + Ks[2][64][68] + Vs[2][64][72]
//     = 106496 B
// ---------------------------------------------------------------------------
#define AKL 68
#define AVL 72
#define QSTG (128 * AKL)
#define KSTG (64 * AKL)
#define VSTG (64 * AVL)

__global__ __launch_bounds__(128) void attn_tf32_reg()
{
    extern __shared__ float sm[];
    float* Qs = sm;                                   // 128*68, then P strips
    float* Ksb[2] = { sm + QSTG,           sm + QSTG + KSTG };
    float* Vsb[2] = { sm + QSTG + 2 * KSTG, sm + QSTG + 2 * KSTG + VSTG };

    const int bh = blockIdx.x;   // b*16 + h
    const int b = bh >> 4;
    const int h = bh & 15;
    const int qt = blockIdx.y;   // 0..7, 128 rows each
    const int tid = threadIdx.x;
    const int w = tid >> 5;
    const int lane = tid & 31;
    const int g = lane >> 2;
    const int t = lane & 3;

    const float* Kg = g_k + (size_t)bh * 1024 * 64;
    const float* Vg = g_v + (size_t)bh * 1024 * 64;

    // prologue: kt=0 K/V via cp.async
#pragma unroll
    for (int i = 0; i < 8; i++) {
        int e = tid + i * 128;
        int r = e >> 4, c = (e & 15) * 4;
        cp_async16(Ksb[0] + r * AKL + c, Kg + (size_t)r * 64 + c);
        cp_async16(Vsb[0] + r * AVL + c, Vg + (size_t)r * 64 + c);
    }
    cp_commit();

    // load Q tile (128 x 64, already tf32)
    {
        const float* Qg = g_q + ((size_t)bh * 1024 + qt * 128) * 64;
#pragma unroll
        for (int i = 0; i < 16; i++) {
            int e = tid + i * 128;          // 0..2047 float4 slots
            int r = e >> 4, c = (e & 15) * 4;
            float4 v = *(const float4*)(Qg + r * 64 + c);
            *(float4*)(Qs + r * AKL + c) = v;
        }
    }
    __syncthreads();

    // Q A-fragments register-resident: qa[rf][ks][4]
    unsigned qa[2][8][4];
#pragma unroll
    for (int rf = 0; rf < 2; rf++) {
        const float* Qw = Qs + (w * 32 + rf * 16) * AKL;
#pragma unroll
        for (int ks = 0; ks < 8; ks++) {
            qa[rf][ks][0] = __float_as_uint(Qw[g * AKL + ks * 8 + t]);
            qa[rf][ks][1] = __float_as_uint(Qw[(g + 8) * AKL + ks * 8 + t]);
            qa[rf][ks][2] = __float_as_uint(Qw[g * AKL + ks * 8 + t + 4]);
            qa[rf][ks][3] = __float_as_uint(Qw[(g + 8) * AKL + ks * 8 + t + 4]);
        }
    }
    __syncthreads();   // Qs now free to act as P

    float o[2][8][4];
#pragma unroll
    for (int rf = 0; rf < 2; rf++)
#pragma unroll
        for (int j = 0; j < 8; j++) {
            o[rf][j][0] = 0.f; o[rf][j][1] = 0.f;
            o[rf][j][2] = 0.f; o[rf][j][3] = 0.f;
        }
    float mr[2][2] = {{-1e30f, -1e30f}, {-1e30f, -1e30f}};   // [rf][0: row g, 1: row g+8]
    float ll[2][2] = {{0.f, 0.f}, {0.f, 0.f}};

    const int qrow = qt * 128 + w * 32 + g;
    // mask word index per (rf, half): row = qrow + rf*16 + half*8
    size_t mbase[2][2];
#pragma unroll
    for (int rf = 0; rf < 2; rf++) {
        mbase[rf][0] = ((size_t)b * 1024 + qrow + rf * 16) * 16;
        mbase[rf][1] = ((size_t)b * 1024 + qrow + rf * 16 + 8) * 16;
    }
    float* Pw = Qs + (w * 32) * AKL;   // per-warp 32-row P strip

    for (int kt = 0; kt < 16; kt++) {
        // issue next K/V, wait current
        if (kt + 1 < 16) {
            float* Kn = Ksb[(kt + 1) & 1];
            float* Vn = Vsb[(kt + 1) & 1];
            const size_t off = (size_t)(kt + 1) * 64 * 64;
#pragma unroll
            for (int i = 0; i < 8; i++) {
                int e = tid + i * 128;
                int r = e >> 4, c = (e & 15) * 4;
                cp_async16(Kn + r * AKL + c, Kg + off + (size_t)r * 64 + c);
                cp_async16(Vn + r * AVL + c, Vg + off + (size_t)r * 64 + c);
            }
            cp_commit();
            asm volatile("cp.async.wait_group 1;");
        } else {
            asm volatile("cp.async.wait_group 0;");
        }
        __syncthreads();

        const float* Ks = Ksb[kt & 1];
        const float* Vs = Vsb[kt & 1];

        // S = Q K^T : per warp 32 x 64; K frag shared across rf
        float s[2][8][4];
#pragma unroll
        for (int j = 0; j < 8; j++) {
            s[0][j][0] = 0.f; s[0][j][1] = 0.f; s[0][j][2] = 0.f; s[0][j][3] = 0.f;
            s[1][j][0] = 0.f; s[1][j][1] = 0.f; s[1][j][2] = 0.f; s[1][j][3] = 0.f;
#pragma unroll
            for (int ks = 0; ks < 8; ks++) {
                unsigned b0 = __float_as_uint(Ks[(j * 8 + g) * AKL + ks * 8 + t]);
                unsigned b1 = __float_as_uint(Ks[(j * 8 + g) * AKL + ks * 8 + t + 4]);
                mma8(s[0][j], qa[0][ks], b0, b1);
                mma8(s[1][j], qa[1][ks], b0, b1);
            }
        }

        // mask + scale + online softmax per rf
#pragma unroll
        for (int rf = 0; rf < 2; rf++) {
            const unsigned long long mb0 = g_maskbits[mbase[rf][0] + kt];
            const unsigned long long mb1 = g_maskbits[mbase[rf][1] + kt];
#pragma unroll
            for (int j = 0; j < 8; j++) {
                int c0 = j * 8 + t * 2;
                s[rf][j][0] = ((mb0 >> c0) & 1ULL) ? s[rf][j][0] * 0.125f : -1e30f;
                s[rf][j][1] = ((mb0 >> (c0 + 1)) & 1ULL) ? s[rf][j][1] * 0.125f : -1e30f;
                s[rf][j][2] = ((mb1 >> c0) & 1ULL) ? s[rf][j][2] * 0.125f : -1e30f;
                s[rf][j][3] = ((mb1 >> (c0 + 1)) & 1ULL) ? s[rf][j][3] * 0.125f : -1e30f;
            }

            float rm0 = -1e30f, rm1 = -1e30f;
#pragma unroll
            for (int j = 0; j < 8; j++) {
                rm0 = fmaxf(rm0, fmaxf(s[rf][j][0], s[rf][j][1]));
                rm1 = fmaxf(rm1, fmaxf(s[rf][j][2], s[rf][j][3]));
            }
            rm0 = fmaxf(rm0, __shfl_xor_sync(0xffffffffu, rm0, 1));
            rm0 = fmaxf(rm0, __shfl_xor_sync(0xffffffffu, rm0, 2));
            rm1 = fmaxf(rm1, __shfl_xor_sync(0xffffffffu, rm1, 1));
            rm1 = fmaxf(rm1, __shfl_xor_sync(0xffffffffu, rm1, 2));

            float mn0 = fmaxf(mr[rf][0], rm0), mn1 = fmaxf(mr[rf][1], rm1);
            float al0 = __expf(mr[rf][0] - mn0), al1 = __expf(mr[rf][1] - mn1);
            float sum0 = 0.f, sum1 = 0.f;
#pragma unroll
            for (int j = 0; j < 8; j++) {
                float p0 = __expf(s[rf][j][0] - mn0);
                float p1 = __expf(s[rf][j][1] - mn0);
                float p2 = __expf(s[rf][j][2] - mn1);
                float p3 = __expf(s[rf][j][3] - mn1);
                s[rf][j][0] = p0; s[rf][j][1] = p1; s[rf][j][2] = p2; s[rf][j][3] = p3;
                sum0 += p0 + p1; sum1 += p2 + p3;
            }
            sum0 += __shfl_xor_sync(0xffffffffu, sum0, 1);
            sum0 += __shfl_xor_sync(0xffffffffu, sum0, 2);
            sum1 += __shfl_xor_sync(0xffffffffu, sum1, 1);
            sum1 += __shfl_xor_sync(0xffffffffu, sum1, 2);
            ll[rf][0] = ll[rf][0] * al0 + sum0; mr[rf][0] = mn0;
            ll[rf][1] = ll[rf][1] * al1 + sum1; mr[rf][1] = mn1;
#pragma unroll
            for (int j = 0; j < 8; j++) {
                o[rf][j][0] *= al0; o[rf][j][1] *= al0;
                o[rf][j][2] *= al1; o[rf][j][3] *= al1;
            }

            // P -> per-warp smem strip (tf32)
            float* Prf = Pw + rf * 16 * AKL;
#pragma unroll
            for (int j = 0; j < 8; j++) {
                float2 p01 = make_float2(to_tf32(s[rf][j][0]), to_tf32(s[rf][j][1]));
                *(float2*)(Prf + g * AKL + j * 8 + t * 2) = p01;
                float2 p23 = make_float2(to_tf32(s[rf][j][2]), to_tf32(s[rf][j][3]));
                *(float2*)(Prf + (g + 8) * AKL + j * 8 + t * 2) = p23;
            }
        }
        __syncwarp();

        // O += P V : V frag shared across rf
#pragma unroll
        for (int ks = 0; ks < 8; ks++) {
            unsigned pa[2][4];
#pragma unroll
            for (int rf = 0; rf < 2; rf++) {
                const float* Prf = Pw + rf * 16 * AKL;
                pa[rf][0] = __float_as_uint(Prf[g * AKL + ks * 8 + t]);
                pa[rf][1] = __float_as_uint(Prf[(g + 8) * AKL + ks * 8 + t]);
                pa[rf][2] = __float_as_uint(Prf[g * AKL + ks * 8 + t + 4]);
                pa[rf][3] = __float_as_uint(Prf[(g + 8) * AKL + ks * 8 + t + 4]);
            }
#pragma unroll
            for (int j = 0; j < 8; j++) {
                unsigned b0 = __float_as_uint(Vs[(ks * 8 + t) * AVL + j * 8 + g]);
                unsigned b1 = __float_as_uint(Vs[(ks * 8 + t + 4) * AVL + j * 8 + g]);
                mma8(o[0][j], pa[0], b0, b1);
                mma8(o[1][j], pa[1], b0, b1);
            }
        }
        __syncthreads();   // Ks/Vs/P reads done before next iteration
    }

    // normalize + write out (tf32-rounded for gemm2): row = lq*8+b, col = h*64+c
#pragma unroll
    for (int rf = 0; rf < 2; rf++) {
        const float inv0 = 1.f / ll[rf][0], inv1 = 1.f / ll[rf][1];
        const int lq0 = qt * 128 + w * 32 + rf * 16 + g;
#pragma unroll
        for (int j = 0; j < 8; j++) {
            float2 o01 = make_float2(to_tf32(o[rf][j][0] * inv0), to_tf32(o[rf][j][1] * inv0));
            *(float2*)(g_attn + ((size_t)lq0 * 8 + b) * 1024 + h * 64 + j * 8 + t * 2) = o01;
            float2 o23 = make_float2(to_tf32(o[rf][j][2] * inv1), to_tf32(o[rf][j][3] * inv1));
            *(float2*)(g_attn + ((size_t)(lq0 + 8) * 8 + b) * 1024 + h * 64 + j * 8 + t * 2) = o23;
        }
    }
}

// ---------------------------------------------------------------------------
// Final bias add
// ---------------------------------------------------------------------------
__global__ __launch_bounds__(256) void bias_add_kernel(float* __restrict__ out,
                                                       const float* __restrict__ bo)
{
    const int m = blockIdx.x;
    const int c = threadIdx.x * 4;
    float4 o = *(float4*)(out + (size_t)m * 1024 + c);
    float4 bb = *(const float4*)(bo + c);
    o.x += bb.x; o.y += bb.y; o.z += bb.z; o.w += bb.w;
    *(float4*)(out + (size_t)m * 1024 + c) = o;
}

// ---------------------------------------------------------------------------
// Launch
// ---------------------------------------------------------------------------
extern "C" void kernel_launch(void* const* d_in, const int* in_sizes, int n_in,
                              void* d_out, int out_size)
{
    const float* hs   = (const float*)d_in[0];
    const float* rpe  = (const float*)d_in[1];
    const void* maskp = d_in[2];
    const float* Wqkv = (const float*)d_in[3];
    const float* bqkv = (const float*)d_in[4];
    const float* Wo   = (const float*)d_in[5];
    const float* bo   = (const float*)d_in[6];
    float* out        = (float*)d_out;

    float *hs_p, *wqkv_p, *wo_p, *qkv_p, *attn_p;
    cudaGetSymbolAddress((void**)&hs_p, g_hs);
    cudaGetSymbolAddress((void**)&wqkv_p, g_wqkv);
    cudaGetSymbolAddress((void**)&wo_p, g_wo);
    cudaGetSymbolAddress((void**)&qkv_p, g_qkv);
    cudaGetSymbolAddress((void**)&attn_p, g_attn);

    // Stage 0: mask canonicalization + operand pre-rounding
    detect_mask_mode_kernel<<<1, 256>>>((const unsigned char*)maskp);
    convert_mask_bits_kernel<<<131072 / 256, 256>>>(maskp);
    tf32_round_kernel<<<(8388608 / 4) / 256, 256>>>(hs_p, hs, 8388608 / 4);
    tf32_round_kernel<<<(3145728 / 4) / 256, 256>>>(wqkv_p, Wqkv, 3145728 / 4);
    tf32_round_kernel<<<(1048576 / 4) / 256, 256>>>(wo_p, Wo, 1048576 / 4);

    const int gemm_smem = 2 * (ASTG + BSTG) * sizeof(float);   // 110592
    cudaFuncSetAttribute(gemm_nt_tf32,
                         cudaFuncAttributeMaxDynamicSharedMemorySize, gemm_smem);

    // Stage 1: QKV projection (bias deferred to rope)
    {
        dim3 grid(3072 / 256, 8192 / 128);
        gemm_nt_tf32<<<grid, 256, gemm_smem>>>(hs_p, wqkv_p, qkv_p, 8192, 3072, 1024);
    }

    // Stage 2: RoPE + bqkv + transpose (tf32-rounded q/k/v)
    rope_bias_transpose_kernel<<<8192, 256>>>(rpe, bqkv);

    // Stage 3: attention
    {
        const int smem = (QSTG + 2 * KSTG + 2 * VSTG) * sizeof(float);  // 106496
        cudaFuncSetAttribute(attn_tf32_reg,
                             cudaFuncAttributeMaxDynamicSharedMemorySize, smem);
        dim3 grid(128, 8);
        attn_tf32_reg<<<grid, 128, smem>>>();
    }

    // Stage 4: output projection + bias
    {
        dim3 grid(1024 / 256, 8192 / 128);
        gemm_nt_tf32<<<grid, 256, gemm_smem>>>(attn_p, wo_p, out, 8192, 1024, 1024);
        bias_add_kernel<<<8192, 256>>>(out, bo);
    }
}

// round 9
// speedup vs baseline: 5.0988x; 2.2802x over previous
#include <cuda_runtime.h>
#include <mma.h>
#include <cstdint>

using namespace nvcuda;

// ---------------------------------------------------------------------------
// VisionSdpaAttention — v6: dual-path GEMM (tcgen05 if 'a'-target, wmma else)
//   L=1024, B=8, C=1024, H=16, D=64
// ---------------------------------------------------------------------------

#if defined(__CUDA_ARCH_FEAT_SM103_ALL) || defined(__CUDA_ARCH_FEAT_SM100_ALL)
#define HAS_TCGEN05 1
#else
#define HAS_TCGEN05 0
#endif

__device__ float g_hs[8388608];               // tf32-rounded hidden_states
__device__ float g_wqkv[3145728];             // tf32-rounded Wqkv
__device__ float g_wo[1048576];               // tf32-rounded Wo
__device__ float g_qkv[25165824];             // (L*B, 3C)
__device__ float g_q[8388608];                // (B,H,L,D) tf32-rounded
__device__ float g_k[8388608];
__device__ float g_v[8388608];
__device__ float g_attn[8388608];             // (L*B, C) tf32-rounded
__device__ unsigned long long g_maskbits[131072];  // [B][L][16 chunks of 64]
__device__ int g_mask_mode;
__device__ int g_use_tc;                      // 1 iff tcgen05 path compiled in

__device__ __forceinline__ float to_tf32(float x) {
    unsigned int u;
    asm("cvt.rna.tf32.f32 %0, %1;" : "=r"(u) : "f"(x));
    return __uint_as_float(u);
}

__device__ __forceinline__ void cp_async16(void* sptr, const void* gptr) {
    unsigned s = (unsigned)__cvta_generic_to_shared(sptr);
    asm volatile("cp.async.cg.shared.global [%0], [%1], 16;" :: "r"(s), "l"(gptr));
}
__device__ __forceinline__ void cp_async16s(uint32_t saddr, const void* gptr) {
    asm volatile("cp.async.cg.shared.global [%0], [%1], 16;" :: "r"(saddr), "l"(gptr));
}
__device__ __forceinline__ void cp_commit() {
    asm volatile("cp.async.commit_group;");
}

// legacy mma.sync m16n8k8 tf32
__device__ __forceinline__ void mma8(float* c, const unsigned* a, unsigned b0, unsigned b1) {
    asm volatile(
        "mma.sync.aligned.m16n8k8.row.col.f32.tf32.tf32.f32 "
        "{%0,%1,%2,%3},{%4,%5,%6,%7},{%8,%9},{%0,%1,%2,%3};"
        : "+f"(c[0]), "+f"(c[1]), "+f"(c[2]), "+f"(c[3])
        : "r"(a[0]), "r"(a[1]), "r"(a[2]), "r"(a[3]), "r"(b0), "r"(b1));
}

__device__ __forceinline__ uint32_t smem_u32(const void* p) {
    return (uint32_t)__cvta_generic_to_shared(p);
}

// ---------------------------------------------------------------------------
// Probe: record whether tcgen05 path exists in the running cubin
// ---------------------------------------------------------------------------
__global__ void probe_tc_kernel()
{
    if (threadIdx.x == 0) g_use_tc = HAS_TCGEN05;
}

// ---------------------------------------------------------------------------
// tf32 rounding copy
// ---------------------------------------------------------------------------
__global__ __launch_bounds__(256) void tf32_round_kernel(
    float* __restrict__ dst, const float* __restrict__ src, int n4)
{
    int i = blockIdx.x * 256 + threadIdx.x;
    if (i >= n4) return;
    float4 v = *((const float4*)src + i);
    v.x = to_tf32(v.x); v.y = to_tf32(v.y);
    v.z = to_tf32(v.z); v.w = to_tf32(v.w);
    *((float4*)dst + i) = v;
}

// ---------------------------------------------------------------------------
// Mask detection + bitpack
// ---------------------------------------------------------------------------
__global__ void detect_mask_mode_kernel(const unsigned char* __restrict__ m)
{
    __shared__ int s1, s23;
    const int tid = threadIdx.x;
    if (tid == 0) { s1 = 0; s23 = 0; }
    __syncthreads();
    bool o1 = false, o23 = false;
    for (int i = tid * 4; i < 16384; i += 1024) {
        if (m[i + 1] != 0) o1 = true;
        if (m[i + 2] != 0 || m[i + 3] != 0) o23 = true;
    }
    if (o1) atomicOr(&s1, 1);
    if (o23) atomicOr(&s23, 1);
    __syncthreads();
    if (tid == 0) g_mask_mode = s1 ? 0 : (s23 ? 2 : 1);
}

__global__ __launch_bounds__(256) void convert_mask_bits_kernel(const void* __restrict__ mp)
{
    const int idx = blockIdx.x * 256 + threadIdx.x;
    const int mode = g_mask_mode;
    unsigned long long bits = 0ULL;
    const size_t base = (size_t)idx * 64;
    if (mode == 0) {
        const uint4* p = (const uint4*)((const unsigned char*)mp + base);
#pragma unroll
        for (int wrd = 0; wrd < 4; wrd++) {
            uint4 v = p[wrd];
            unsigned ws[4] = {v.x, v.y, v.z, v.w};
#pragma unroll
            for (int q = 0; q < 4; q++)
#pragma unroll
                for (int by = 0; by < 4; by++)
                    if ((ws[q] >> (by * 8)) & 0xffu)
                        bits |= 1ULL << (wrd * 16 + q * 4 + by);
        }
    } else if (mode == 1) {
        const int* p = (const int*)mp + base;
#pragma unroll 8
        for (int j = 0; j < 64; j++)
            if (p[j] != 0) bits |= 1ULL << j;
    } else {
        const float* p = (const float*)mp + base;
#pragma unroll 8
        for (int j = 0; j < 64; j++)
            if (p[j] != 0.0f) bits |= 1ULL << j;
    }
    g_maskbits[idx] = bits;
}

// ===========================================================================
// Path A: tcgen05 GEMM (compiled only under an 'a' target)
// Tile 128x256, BK=32 floats (SW128 atoms), double-buffered cp.async.
// ===========================================================================
#define TCSTAGE 49152
#define TCB_OFF 16384

#if HAS_TCGEN05
__device__ __forceinline__ uint32_t elect_one_pred() {
    uint32_t pred;
    asm volatile(
        "{\n\t.reg .pred p;\n\telect.sync _|p, 0xFFFFFFFF;\n\t"
        "selp.b32 %0, 1, 0, p;\n\t}" : "=r"(pred));
    return pred;
}

static __device__ __forceinline__ uint64_t make_desc_sw128(uint32_t addr) {
    return ((uint64_t)2u << 61) | ((uint64_t)1u << 46) | ((uint64_t)64u << 32)
         | ((uint64_t)1u << 16) | ((uint64_t)(addr >> 4) & 0x3FFFu);
}

__device__ __forceinline__ void tcgen05_mma_tf32_ss(
    uint32_t d_tmem, uint64_t a_desc, uint64_t b_desc, uint32_t idesc, bool enable_d)
{
    uint32_t en = enable_d ? 1u : 0u;
    asm volatile(
        "{\n\t.reg .pred p;\n\t"
        "setp.ne.u32 p, %5, 0;\n\t"
        "tcgen05.mma.cta_group::1.kind::tf32 [%0], %1, %2, %3, {%4, %4, %4, %4}, p;\n\t"
        "}"
        :: "r"(d_tmem), "l"(a_desc), "l"(b_desc), "r"(idesc), "r"(0u), "r"(en)
        : "memory");
}

// idesc: D=F32(1)<<4 | A=TF32(2)<<7 | B=TF32(2)<<10 | (N/8)<<17 | (M/16)<<24
static constexpr uint32_t TC_IDESC =
    (1u << 4) | (2u << 7) | (2u << 10) | ((256u / 8) << 17) | ((128u / 16) << 24);
#endif

__global__ __launch_bounds__(128) void gemm_tc_tf32(
    const float* __restrict__ A, const float* __restrict__ B,
    float* __restrict__ C, int M, int N, int K)
{
#if HAS_TCGEN05
    extern __shared__ char smem[];
    const uint32_t sb = smem_u32(smem);
    const uint32_t ctrl = sb;                              // [0]=tmem ptr, [8]=mbar
    const uint32_t data = (sb + 16 + 1023) & ~1023u;

    const int bm = blockIdx.y * 128;
    const int bn = blockIdx.x * 256;
    const int tid = threadIdx.x;
    const int wid = tid >> 5;
    const int lane = tid & 31;

    if (wid == 0) {
        asm volatile("tcgen05.alloc.cta_group::1.sync.aligned.shared::cta.b32 [%0], %1;"
            :: "r"(ctrl), "r"(256u) : "memory");
        asm volatile("tcgen05.relinquish_alloc_permit.cta_group::1.sync.aligned;");
    }
    __syncthreads();
    uint32_t tmem;
    asm volatile("ld.shared.b32 %0, [%1];" : "=r"(tmem) : "r"(ctrl));
    if (tid == 0)
        asm volatile("mbarrier.init.shared.b64 [%0], %1;" :: "r"(ctrl + 8), "r"(1u) : "memory");
    __syncthreads();

    const int nk = K / 32;

    auto load_chunk = [&](int it) {
        const uint32_t st = data + (uint32_t)(it & 1) * TCSTAGE;
        const int k0 = it * 32;
#pragma unroll
        for (int i = 0; i < 8; i++) {
            int e = tid + i * 128;
            int r = e >> 3, c = e & 7;
            uint32_t byte = (uint32_t)(r * 128 + c * 16);
            uint32_t sw = byte ^ ((byte >> 3) & 0x70u);
            cp_async16s(st + sw, A + (size_t)(bm + r) * K + k0 + c * 4);
        }
#pragma unroll
        for (int i = 0; i < 16; i++) {
            int e = tid + i * 128;
            int r = e >> 3, c = e & 7;
            uint32_t byte = (uint32_t)(r * 128 + c * 16);
            uint32_t sw = byte ^ ((byte >> 3) & 0x70u);
            cp_async16s(st + TCB_OFF + sw, B + (size_t)(bn + r) * K + k0 + c * 4);
        }
        cp_commit();
    };

    load_chunk(0);

    for (int it = 0; it < nk; it++) {
        asm volatile("cp.async.wait_group 0;");
        __syncthreads();
        asm volatile("fence.proxy.async.shared::cta;" ::: "memory");
        if (wid == 0) {
            const uint32_t st = data + (uint32_t)(it & 1) * TCSTAGE;
            uint64_t ad = make_desc_sw128(st);
            uint64_t bd = make_desc_sw128(st + TCB_OFF);
            if (elect_one_pred()) {
#pragma unroll
                for (int ks = 0; ks < 4; ks++)
                    tcgen05_mma_tf32_ss(tmem, ad + ks * 2, bd + ks * 2, TC_IDESC,
                                        (it != 0) || (ks != 0));
                asm volatile(
                    "tcgen05.commit.cta_group::1.mbarrier::arrive::one.shared::cluster.b64 [%0];"
                    :: "r"(ctrl + 8) : "memory");
            }
        }
        if (it + 1 < nk) load_chunk(it + 1);
        // wait MMA of chunk `it` (frees its smem stage for it+2's loads)
        {
            uint32_t par = (uint32_t)(it & 1);
            asm volatile(
                "{\n\t.reg .pred P1;\n\t"
                "WAIT_LOOP_%=:\n\t"
                "mbarrier.try_wait.parity.acquire.cta.shared::cta.b64 P1, [%0], %1, 0x989680;\n\t"
                "@P1 bra.uni WAIT_DONE_%=;\n\t"
                "bra.uni WAIT_LOOP_%=;\n\t"
                "WAIT_DONE_%=:\n\t}"
                :: "r"(ctrl + 8), "r"(par) : "memory");
        }
    }

    asm volatile("tcgen05.fence::after_thread_sync;" ::: "memory");

    // epilogue: thread row = bm + wid*32 + lane; 8 batches of 32 cols
    {
        float* Crow = C + (size_t)(bm + wid * 32 + lane) * N + bn;
#pragma unroll
        for (int bt = 0; bt < 8; bt++) {
            uint32_t r32[32];
            asm volatile(
                "tcgen05.ld.sync.aligned.32x32b.x32.b32 "
                "{%0, %1, %2, %3, %4, %5, %6, %7, "
                " %8, %9, %10, %11, %12, %13, %14, %15, "
                " %16, %17, %18, %19, %20, %21, %22, %23, "
                " %24, %25, %26, %27, %28, %29, %30, %31}, [%32];"
                : "=r"(r32[0]),  "=r"(r32[1]),  "=r"(r32[2]),  "=r"(r32[3]),
                  "=r"(r32[4]),  "=r"(r32[5]),  "=r"(r32[6]),  "=r"(r32[7]),
                  "=r"(r32[8]),  "=r"(r32[9]),  "=r"(r32[10]), "=r"(r32[11]),
                  "=r"(r32[12]), "=r"(r32[13]), "=r"(r32[14]), "=r"(r32[15]),
                  "=r"(r32[16]), "=r"(r32[17]), "=r"(r32[18]), "=r"(r32[19]),
                  "=r"(r32[20]), "=r"(r32[21]), "=r"(r32[22]), "=r"(r32[23]),
                  "=r"(r32[24]), "=r"(r32[25]), "=r"(r32[26]), "=r"(r32[27]),
                  "=r"(r32[28]), "=r"(r32[29]), "=r"(r32[30]), "=r"(r32[31])
                : "r"(tmem + bt * 32));
            asm volatile("tcgen05.wait::ld.sync.aligned;" ::: "memory");
#pragma unroll
            for (int q = 0; q < 8; q++) {
                float4 o;
                o.x = __uint_as_float(r32[q * 4 + 0]);
                o.y = __uint_as_float(r32[q * 4 + 1]);
                o.z = __uint_as_float(r32[q * 4 + 2]);
                o.w = __uint_as_float(r32[q * 4 + 3]);
                *(float4*)(Crow + bt * 32 + q * 4) = o;
            }
        }
    }

    __syncthreads();
    if (tid == 0)
        asm volatile("mbarrier.inval.shared.b64 [%0];" :: "r"(ctrl + 8) : "memory");
    __syncthreads();
    if (wid == 0) {
        asm volatile("tcgen05.dealloc.cta_group::1.sync.aligned.b32 %0, %1;"
            :: "r"(tmem), "r"(256u));
    }
#else
    // tcgen05 unavailable in this compilation: no-op (wmma kernel does the work)
    (void)A; (void)B; (void)C; (void)M; (void)N; (void)K;
#endif
}

// ===========================================================================
// Path B: wmma TF32 GEMM NT (fallback): C = A * B^T
// BM=128, BN=256, BK=32; 256 threads = 8 warps (2M x 4N), warp tile 64x64.
// cp.async double buffer, ONE __syncthreads per k-chunk.
// ===========================================================================
#define GLDA 36
#define ASTG (128 * GLDA)
#define BSTG (256 * GLDA)

__global__ __launch_bounds__(256) void gemm_wmma_tf32(
    const float* __restrict__ A, const float* __restrict__ B,
    float* __restrict__ C, int M, int N, int K)
{
    if (g_use_tc) return;   // tcgen05 path active

    extern __shared__ float sg[];
    float* Asb[2] = { sg,            sg + ASTG };
    float* Bsb[2] = { sg + 2 * ASTG, sg + 2 * ASTG + BSTG };

    const int bm = blockIdx.y * 128;
    const int bn = blockIdx.x * 256;
    const int tid = threadIdx.x;
    const int wid = tid >> 5;
    const int warpM = wid & 1;
    const int warpN = wid >> 1;

    wmma::fragment<wmma::accumulator, 16, 16, 8, float> acc[4][4];
#pragma unroll
    for (int i = 0; i < 4; i++)
#pragma unroll
        for (int j = 0; j < 4; j++) wmma::fill_fragment(acc[i][j], 0.0f);

    const int nk = K / 32;

    auto load_chunk = [&](int it) {
        const int k0 = it * 32;
        float* As = Asb[it & 1];
        float* Bs = Bsb[it & 1];
#pragma unroll
        for (int i = 0; i < 4; i++) {
            int e = tid + i * 256;
            int r = e >> 3, c = (e & 7) * 4;
            cp_async16(As + r * GLDA + c, A + (size_t)(bm + r) * K + k0 + c);
        }
#pragma unroll
        for (int i = 0; i < 8; i++) {
            int e = tid + i * 256;
            int r = e >> 3, c = (e & 7) * 4;
            cp_async16(Bs + r * GLDA + c, B + (size_t)(bn + r) * K + k0 + c);
        }
        cp_commit();
    };

    load_chunk(0);

    for (int it = 0; it < nk; it++) {
        asm volatile("cp.async.wait_group 0;");
        __syncthreads();                    // chunk `it` visible; prev compute done
        if (it + 1 < nk) load_chunk(it + 1);

        const float* As = Asb[it & 1];
        const float* Bs = Bsb[it & 1];
#pragma unroll
        for (int ks = 0; ks < 4; ks++) {
            wmma::fragment<wmma::matrix_a, 16, 16, 8, wmma::precision::tf32, wmma::row_major> af[4];
            wmma::fragment<wmma::matrix_b, 16, 16, 8, wmma::precision::tf32, wmma::col_major> bf[4];
#pragma unroll
            for (int i = 0; i < 4; i++)
                wmma::load_matrix_sync(af[i], As + (warpM * 64 + i * 16) * GLDA + ks * 8, GLDA);
#pragma unroll
            for (int j = 0; j < 4; j++)
                wmma::load_matrix_sync(bf[j], Bs + (warpN * 64 + j * 16) * GLDA + ks * 8, GLDA);
#pragma unroll
            for (int i = 0; i < 4; i++)
#pragma unroll
                for (int j = 0; j < 4; j++)
                    wmma::mma_sync(acc[i][j], af[i], bf[j], acc[i][j]);
        }
    }

#pragma unroll
    for (int i = 0; i < 4; i++)
#pragma unroll
        for (int j = 0; j < 4; j++)
            wmma::store_matrix_sync(
                C + (size_t)(bm + warpM * 64 + i * 16) * N + bn + warpN * 64 + j * 16,
                acc[i][j], N, wmma::mem_row_major);
}

// ---------------------------------------------------------------------------
// RoPE + bias + transpose, tf32-rounded stores
// ---------------------------------------------------------------------------
__global__ __launch_bounds__(256) void rope_bias_transpose_kernel(
    const float* __restrict__ rpe, const float* __restrict__ bq)
{
    __shared__ float cs[32], sn[32];
    const int m = blockIdx.x;   // l*8 + b
    const int l = m >> 3;
    const int b = m & 7;
    const int tid = threadIdx.x;
    if (tid < 32) {
        float a = rpe[l * 32 + tid];
        cs[tid] = cosf(a);
        sn[tid] = sinf(a);
    }
    __syncthreads();
    const float* src = g_qkv + (size_t)m * 3072;
    for (int r = tid; r < 3072; r += 256) {
        int which = r >> 10;
        int hh = (r >> 6) & 15;
        int d = r & 63;
        float x = src[r] + bq[r];
        float val;
        if (which < 2) {
            float xp = src[r ^ 1] + bq[r ^ 1];
            float c = cs[d & 31];
            float s = sn[d & 31];
            val = x * c + ((d & 1) ? xp : -xp) * s;
        } else {
            val = x;
        }
        float* dst = (which == 0) ? g_q : (which == 1) ? g_k : g_v;
        dst[(((size_t)(b * 16 + hh)) * 1024 + l) * 64 + d] = to_tf32(val);
    }
}

// ---------------------------------------------------------------------------
// Flash attention (mma.sync tf32, 32 Q rows/warp), ONE sync per kt iteration.
// ---------------------------------------------------------------------------
#define AKL 68
#define AVL 72
#define QSTG (128 * AKL)
#define KSTG (64 * AKL)
#define VSTG (64 * AVL)

__global__ __launch_bounds__(128) void attn_tf32_reg()
{
    extern __shared__ float sm[];
    float* Qs = sm;
    float* Ksb[2] = { sm + QSTG,            sm + QSTG + KSTG };
    float* Vsb[2] = { sm + QSTG + 2 * KSTG, sm + QSTG + 2 * KSTG + VSTG };

    const int bh = blockIdx.x;
    const int b = bh >> 4;
    const int h = bh & 15;
    const int qt = blockIdx.y;
    const int tid = threadIdx.x;
    const int w = tid >> 5;
    const int lane = tid & 31;
    const int g = lane >> 2;
    const int t = lane & 3;

    const float* Kg = g_k + (size_t)bh * 1024 * 64;
    const float* Vg = g_v + (size_t)bh * 1024 * 64;

    auto load_kv = [&](int kt) {
        float* Kd = Ksb[kt & 1];
        float* Vd = Vsb[kt & 1];
        const size_t off = (size_t)kt * 64 * 64;
#pragma unroll
        for (int i = 0; i < 8; i++) {
            int e = tid + i * 128;
            int r = e >> 4, c = (e & 15) * 4;
            cp_async16(Kd + r * AKL + c, Kg + off + (size_t)r * 64 + c);
            cp_async16(Vd + r * AVL + c, Vg + off + (size_t)r * 64 + c);
        }
        cp_commit();
    };

    load_kv(0);

    {
        const float* Qg = g_q + ((size_t)bh * 1024 + qt * 128) * 64;
#pragma unroll
        for (int i = 0; i < 16; i++) {
            int e = tid + i * 128;
            int r = e >> 4, c = (e & 15) * 4;
            float4 v = *(const float4*)(Qg + r * 64 + c);
            *(float4*)(Qs + r * AKL + c) = v;
        }
    }
    __syncthreads();

    unsigned qa[2][8][4];
#pragma unroll
    for (int rf = 0; rf < 2; rf++) {
        const float* Qw = Qs + (w * 32 + rf * 16) * AKL;
#pragma unroll
        for (int ks = 0; ks < 8; ks++) {
            qa[rf][ks][0] = __float_as_uint(Qw[g * AKL + ks * 8 + t]);
            qa[rf][ks][1] = __float_as_uint(Qw[(g + 8) * AKL + ks * 8 + t]);
            qa[rf][ks][2] = __float_as_uint(Qw[g * AKL + ks * 8 + t + 4]);
            qa[rf][ks][3] = __float_as_uint(Qw[(g + 8) * AKL + ks * 8 + t + 4]);
        }
    }
    __syncthreads();   // Qs becomes P strips

    float o[2][8][4];
#pragma unroll
    for (int rf = 0; rf < 2; rf++)
#pragma unroll
        for (int j = 0; j < 8; j++) {
            o[rf][j][0] = 0.f; o[rf][j][1] = 0.f;
            o[rf][j][2] = 0.f; o[rf][j][3] = 0.f;
        }
    float mr[2][2] = {{-1e30f, -1e30f}, {-1e30f, -1e30f}};
    float ll[2][2] = {{0.f, 0.f}, {0.f, 0.f}};

    const int qrow = qt * 128 + w * 32 + g;
    size_t mbase[2][2];
#pragma unroll
    for (int rf = 0; rf < 2; rf++) {
        mbase[rf][0] = ((size_t)b * 1024 + qrow + rf * 16) * 16;
        mbase[rf][1] = ((size_t)b * 1024 + qrow + rf * 16 + 8) * 16;
    }
    float* Pw = Qs + (w * 32) * AKL;

    for (int kt = 0; kt < 16; kt++) {
        asm volatile("cp.async.wait_group 0;");
        __syncthreads();                 // K/V kt visible; prev compute done
        if (kt + 1 < 16) load_kv(kt + 1);

        const float* Ks = Ksb[kt & 1];
        const float* Vs = Vsb[kt & 1];

        float s[2][8][4];
#pragma unroll
        for (int j = 0; j < 8; j++) {
            s[0][j][0] = 0.f; s[0][j][1] = 0.f; s[0][j][2] = 0.f; s[0][j][3] = 0.f;
            s[1][j][0] = 0.f; s[1][j][1] = 0.f; s[1][j][2] = 0.f; s[1][j][3] = 0.f;
#pragma unroll
            for (int ks = 0; ks < 8; ks++) {
                unsigned b0 = __float_as_uint(Ks[(j * 8 + g) * AKL + ks * 8 + t]);
                unsigned b1 = __float_as_uint(Ks[(j * 8 + g) * AKL + ks * 8 + t + 4]);
                mma8(s[0][j], qa[0][ks], b0, b1);
                mma8(s[1][j], qa[1][ks], b0, b1);
            }
        }

#pragma unroll
        for (int rf = 0; rf < 2; rf++) {
            const unsigned long long mb0 = g_maskbits[mbase[rf][0] + kt];
            const unsigned long long mb1 = g_maskbits[mbase[rf][1] + kt];
#pragma unroll
            for (int j = 0; j < 8; j++) {
                int c0 = j * 8 + t * 2;
                s[rf][j][0] = ((mb0 >> c0) & 1ULL) ? s[rf][j][0] * 0.125f : -1e30f;
                s[rf][j][1] = ((mb0 >> (c0 + 1)) & 1ULL) ? s[rf][j][1] * 0.125f : -1e30f;
                s[rf][j][2] = ((mb1 >> c0) & 1ULL) ? s[rf][j][2] * 0.125f : -1e30f;
                s[rf][j][3] = ((mb1 >> (c0 + 1)) & 1ULL) ? s[rf][j][3] * 0.125f : -1e30f;
            }

            float rm0 = -1e30f, rm1 = -1e30f;
#pragma unroll
            for (int j = 0; j < 8; j++) {
                rm0 = fmaxf(rm0, fmaxf(s[rf][j][0], s[rf][j][1]));
                rm1 = fmaxf(rm1, fmaxf(s[rf][j][2], s[rf][j][3]));
            }
            rm0 = fmaxf(rm0, __shfl_xor_sync(0xffffffffu, rm0, 1));
            rm0 = fmaxf(rm0, __shfl_xor_sync(0xffffffffu, rm0, 2));
            rm1 = fmaxf(rm1, __shfl_xor_sync(0xffffffffu, rm1, 1));
            rm1 = fmaxf(rm1, __shfl_xor_sync(0xffffffffu, rm1, 2));

            float mn0 = fmaxf(mr[rf][0], rm0), mn1 = fmaxf(mr[rf][1], rm1);
            float al0 = __expf(mr[rf][0] - mn0), al1 = __expf(mr[rf][1] - mn1);
            float sum0 = 0.f, sum1 = 0.f;
#pragma unroll
            for (int j = 0; j < 8; j++) {
                float p0 = __expf(s[rf][j][0] - mn0);
                float p1 = __expf(s[rf][j][1] - mn0);
                float p2 = __expf(s[rf][j][2] - mn1);
                float p3 = __expf(s[rf][j][3] - mn1);
                s[rf][j][0] = p0; s[rf][j][1] = p1; s[rf][j][2] = p2; s[rf][j][3] = p3;
                sum0 += p0 + p1; sum1 += p2 + p3;
            }
            sum0 += __shfl_xor_sync(0xffffffffu, sum0, 1);
            sum0 += __shfl_xor_sync(0xffffffffu, sum0, 2);
            sum1 += __shfl_xor_sync(0xffffffffu, sum1, 1);
            sum1 += __shfl_xor_sync(0xffffffffu, sum1, 2);
            ll[rf][0] = ll[rf][0] * al0 + sum0; mr[rf][0] = mn0;
            ll[rf][1] = ll[rf][1] * al1 + sum1; mr[rf][1] = mn1;
#pragma unroll
            for (int j = 0; j < 8; j++) {
                o[rf][j][0] *= al0; o[rf][j][1] *= al0;
                o[rf][j][2] *= al1; o[rf][j][3] *= al1;
            }

            float* Prf = Pw + rf * 16 * AKL;
#pragma unroll
            for (int j = 0; j < 8; j++) {
                float2 p01 = make_float2(to_tf32(s[rf][j][0]), to_tf32(s[rf][j][1]));
                *(float2*)(Prf + g * AKL + j * 8 + t * 2) = p01;
                float2 p23 = make_float2(to_tf32(s[rf][j][2]), to_tf32(s[rf][j][3]));
                *(float2*)(Prf + (g + 8) * AKL + j * 8 + t * 2) = p23;
            }
        }
        __syncwarp();

#pragma unroll
        for (int ks = 0; ks < 8; ks++) {
            unsigned pa[2][4];
#pragma unroll
            for (int rf = 0; rf < 2; rf++) {
                const float* Prf = Pw + rf * 16 * AKL;
                pa[rf][0] = __float_as_uint(Prf[g * AKL + ks * 8 + t]);
                pa[rf][1] = __float_as_uint(Prf[(g + 8) * AKL + ks * 8 + t]);
                pa[rf][2] = __float_as_uint(Prf[g * AKL + ks * 8 + t + 4]);
                pa[rf][3] = __float_as_uint(Prf[(g + 8) * AKL + ks * 8 + t + 4]);
            }
#pragma unroll
            for (int j = 0; j < 8; j++) {
                unsigned b0 = __float_as_uint(Vs[(ks * 8 + t) * AVL + j * 8 + g]);
                unsigned b1 = __float_as_uint(Vs[(ks * 8 + t + 4) * AVL + j * 8 + g]);
                mma8(o[0][j], pa[0], b0, b1);
                mma8(o[1][j], pa[1], b0, b1);
            }
        }
        __syncwarp();   // P strip reads done before next iteration's writes
    }

#pragma unroll
    for (int rf = 0; rf < 2; rf++) {
        const float inv0 = 1.f / ll[rf][0], inv1 = 1.f / ll[rf][1];
        const int lq0 = qt * 128 + w * 32 + rf * 16 + g;
#pragma unroll
        for (int j = 0; j < 8; j++) {
            float2 o01 = make_float2(to_tf32(o[rf][j][0] * inv0), to_tf32(o[rf][j][1] * inv0));
            *(float2*)(g_attn + ((size_t)lq0 * 8 + b) * 1024 + h * 64 + j * 8 + t * 2) = o01;
            float2 o23 = make_float2(to_tf32(o[rf][j][2] * inv1), to_tf32(o[rf][j][3] * inv1));
            *(float2*)(g_attn + ((size_t)(lq0 + 8) * 8 + b) * 1024 + h * 64 + j * 8 + t * 2) = o23;
        }
    }
}

// ---------------------------------------------------------------------------
// Final bias add
// ---------------------------------------------------------------------------
__global__ __launch_bounds__(256) void bias_add_kernel(float* __restrict__ out,
                                                       const float* __restrict__ bo)
{
    const int m = blockIdx.x;
    const int c = threadIdx.x * 4;
    float4 o = *(float4*)(out + (size_t)m * 1024 + c);
    float4 bb = *(const float4*)(bo + c);
    o.x += bb.x; o.y += bb.y; o.z += bb.z; o.w += bb.w;
    *(float4*)(out + (size_t)m * 1024 + c) = o;
}

// ---------------------------------------------------------------------------
// Launch
// ---------------------------------------------------------------------------
extern "C" void kernel_launch(void* const* d_in, const int* in_sizes, int n_in,
                              void* d_out, int out_size)
{
    const float* hs   = (const float*)d_in[0];
    const float* rpe  = (const float*)d_in[1];
    const void* maskp = d_in[2];
    const float* Wqkv = (const float*)d_in[3];
    const float* bqkv = (const float*)d_in[4];
    const float* Wo   = (const float*)d_in[5];
    const float* bo   = (const float*)d_in[6];
    float* out        = (float*)d_out;

    float *hs_p, *wqkv_p, *wo_p, *qkv_p, *attn_p;
    cudaGetSymbolAddress((void**)&hs_p, g_hs);
    cudaGetSymbolAddress((void**)&wqkv_p, g_wqkv);
    cudaGetSymbolAddress((void**)&wo_p, g_wo);
    cudaGetSymbolAddress((void**)&qkv_p, g_qkv);
    cudaGetSymbolAddress((void**)&attn_p, g_attn);

    // Stage 0: probe + mask canonicalization + operand pre-rounding
    probe_tc_kernel<<<1, 32>>>();
    detect_mask_mode_kernel<<<1, 256>>>((const unsigned char*)maskp);
    convert_mask_bits_kernel<<<131072 / 256, 256>>>(maskp);
    tf32_round_kernel<<<(8388608 / 4) / 256, 256>>>(hs_p, hs, 8388608 / 4);
    tf32_round_kernel<<<(3145728 / 4) / 256, 256>>>(wqkv_p, Wqkv, 3145728 / 4);
    tf32_round_kernel<<<(1048576 / 4) / 256, 256>>>(wo_p, Wo, 1048576 / 4);

    const int tc_smem = 2048 + 2 * TCSTAGE;                   // 100352
    const int wm_smem = 2 * (ASTG + BSTG) * (int)sizeof(float);  // 110592
    cudaFuncSetAttribute(gemm_tc_tf32,
                         cudaFuncAttributeMaxDynamicSharedMemorySize, tc_smem);
    cudaFuncSetAttribute(gemm_wmma_tf32,
                         cudaFuncAttributeMaxDynamicSharedMemorySize, wm_smem);

    // Stage 1: QKV projection (dual path; inactive one no-ops)
    {
        dim3 grid_tc(3072 / 256, 8192 / 128);
        gemm_tc_tf32<<<grid_tc, 128, tc_smem>>>(hs_p, wqkv_p, qkv_p, 8192, 3072, 1024);
        dim3 grid_wm(3072 / 256, 8192 / 128);
        gemm_wmma_tf32<<<grid_wm, 256, wm_smem>>>(hs_p, wqkv_p, qkv_p, 8192, 3072, 1024);
    }

    // Stage 2: RoPE + bqkv + transpose
    rope_bias_transpose_kernel<<<8192, 256>>>(rpe, bqkv);

    // Stage 3: attention
    {
        const int smem = (QSTG + 2 * KSTG + 2 * VSTG) * (int)sizeof(float);  // 106496
        cudaFuncSetAttribute(attn_tf32_reg,
                             cudaFuncAttributeMaxDynamicSharedMemorySize, smem);
        dim3 grid(128, 8);
        attn_tf32_reg<<<grid, 128, smem>>>();
    }

    // Stage 4: output projection (dual path) + bias
    {
        dim3 grid_tc(1024 / 256, 8192 / 128);
        gemm_tc_tf32<<<grid_tc, 128, tc_smem>>>(attn_p, wo_p, out, 8192, 1024, 1024);
        dim3 grid_wm(1024 / 256, 8192 / 128);
        gemm_wmma_tf32<<<grid_wm, 256, wm_smem>>>(attn_p, wo_p, out, 8192, 1024, 1024);
        bias_add_kernel<<<8192, 256>>>(out, bo);
    }
}